// round 1
// baseline (speedup 1.0000x reference)
#include <cuda_runtime.h>
#include <math.h>

// Problem constants (match reference setup_inputs)
#define BB 2
#define CC 16
#define HH 160
#define WW 192
#define SS 3
#define DD 48
#define HWSZ (HH * WW)
#define DCH 16          // depths per block
#define NDCH (DD / DCH) // 3 depth chunks

// Scratch: centered ref features [B][C][H][W] and per-pixel norm [B][H][W]
__device__ float g_f1c[BB * CC * HWSZ];
__device__ float g_n1[BB * HWSZ];

// ---------------------------------------------------------------------------
// Kernel 1: center ref feats over channel axis, store centered values + norm
// ---------------------------------------------------------------------------
__global__ void prep_ref_kernel(const float* __restrict__ ref) {
    int pix = blockIdx.x * blockDim.x + threadIdx.x;
    if (pix >= BB * HWSZ) return;
    int b = pix / HWSZ;
    int p = pix - b * HWSZ;

    float v[CC];
    float sum = 0.f;
#pragma unroll
    for (int c = 0; c < CC; c++) {
        v[c] = ref[(b * CC + c) * HWSZ + p];
        sum += v[c];
    }
    float m = sum * (1.0f / CC);
    float ss = 0.f;
#pragma unroll
    for (int c = 0; c < CC; c++) {
        float cv = v[c] - m;
        ss = fmaf(cv, cv, ss);
        g_f1c[(b * CC + c) * HWSZ + p] = cv;
    }
    g_n1[pix] = sqrtf(ss);
}

// 3x3 inverse via adjugate
__device__ __forceinline__ void inv3x3(const float* K, float* I) {
    float a = K[0], b = K[1], c = K[2];
    float d = K[3], e = K[4], f = K[5];
    float g = K[6], h = K[7], i = K[8];
    float A = e * i - f * h;
    float Bm = -(d * i - f * g);
    float Cm = d * h - e * g;
    float det = a * A + b * Bm + c * Cm;
    float rd = 1.0f / det;
    I[0] = A * rd;
    I[1] = -(b * i - c * h) * rd;
    I[2] = (b * f - c * e) * rd;
    I[3] = Bm * rd;
    I[4] = (a * i - c * g) * rd;
    I[5] = -(a * f - c * d) * rd;
    I[6] = Cm * rd;
    I[7] = -(a * h - b * g) * rd;
    I[8] = (a * e - b * d) * rd;
}

__device__ __forceinline__ void mat3mul(const float* A, const float* B, float* C) {
#pragma unroll
    for (int i = 0; i < 3; i++)
#pragma unroll
        for (int j = 0; j < 3; j++)
            C[i * 3 + j] = A[i * 3 + 0] * B[0 * 3 + j] +
                           A[i * 3 + 1] * B[1 * 3 + j] +
                           A[i * 3 + 2] * B[2 * 3 + j];
}

// ---------------------------------------------------------------------------
// Kernel 2: cost volume. block = one image row (192 threads), one depth chunk.
// grid = (NDCH, H, B)
// ---------------------------------------------------------------------------
__global__ __launch_bounds__(WW, 4) void cost_kernel(
    const float* __restrict__ src,    // [S,B,C,H,W]
    const float* __restrict__ Kref,   // [B,3,3]
    const float* __restrict__ Ksrc,   // [S,B,3,3]
    const float* __restrict__ T,      // [S,B,4,4]
    const float* __restrict__ depths, // [D]
    float* __restrict__ out)          // [B,D,H,W]
{
    const int tx = threadIdx.x;          // w coordinate
    const int h = blockIdx.y;
    const int b = blockIdx.z;
    const int dch = blockIdx.x;

    __shared__ float s_f1c[CC * WW];

    // Load centered ref features for this row into smem (coalesced per channel)
#pragma unroll
    for (int c = 0; c < CC; c++)
        s_f1c[c * WW + tx] = g_f1c[(b * CC + c) * HWSZ + h * WW + tx];
    __syncthreads();

    const float n1 = g_n1[b * HWSZ + h * WW + tx];

    // K^{-1} for this batch
    float Kinv[9];
    inv3x3(Kref + b * 9, Kinv);

    float dh[DCH];
#pragma unroll
    for (int k = 0; k < DCH; k++) dh[k] = depths[dch * DCH + k];

    float cost[DCH];
#pragma unroll
    for (int k = 0; k < DCH; k++) cost[k] = 0.f;

    const float u = (float)tx;
    const float v = (float)h;

    for (int s = 0; s < SS; s++) {
        // M = Ks * R * Kinv ; q = Ks * t
        const float* Tm = T + (s * BB + b) * 16;
        float R[9] = {Tm[0], Tm[1], Tm[2], Tm[4], Tm[5], Tm[6], Tm[8], Tm[9], Tm[10]};
        float t3[3] = {Tm[3], Tm[7], Tm[11]};
        const float* Ks = Ksrc + (s * BB + b) * 9;
        float RK[9], M[9];
        mat3mul(R, Kinv, RK);
        mat3mul(Ks, RK, M);
        float q0 = Ks[0] * t3[0] + Ks[1] * t3[1] + Ks[2] * t3[2];
        float q1 = Ks[3] * t3[0] + Ks[4] * t3[1] + Ks[5] * t3[2];
        float q2 = Ks[6] * t3[0] + Ks[7] * t3[1] + Ks[8] * t3[2];

        // per-pixel homogeneous ray through M (depth-independent part)
        float hp0 = M[0] * u + M[1] * v + M[2];
        float hp1 = M[3] * u + M[4] * v + M[5];
        float hp2 = M[6] * u + M[7] * v + M[8];

        const float* sb = src + (size_t)(s * BB + b) * CC * HWSZ;

#pragma unroll 2
        for (int k = 0; k < DCH; k++) {
            float d = dh[k];
            float p0 = fmaf(d, hp0, q0);
            float p1 = fmaf(d, hp1, q1);
            float p2 = fmaf(d, hp2, q2);

            bool valid = p2 > 0.001f;
            float zs = fmaxf(p2, 0.001f);
            float inz = 1.0f / zs;
            float x = p0 * inz;
            float y = p1 * inz;

            float x0f = floorf(x);
            float y0f = floorf(y);
            float fx = x - x0f;
            float fy = y - y0f;
            int x0 = (int)x0f;
            int y0 = (int)y0f;
            int x1 = x0 + 1;
            int y1 = y0 + 1;

            bool okx0 = (x0 >= 0) & (x0 < WW);
            bool okx1 = (x1 >= 0) & (x1 < WW);
            bool oky0 = (y0 >= 0) & (y0 < HH);
            bool oky1 = (y1 >= 0) & (y1 < HH);

            float w00 = (valid & okx0 & oky0) ? (1.f - fx) * (1.f - fy) : 0.f;
            float w01 = (valid & okx1 & oky0) ? fx * (1.f - fy) : 0.f;
            float w10 = (valid & okx0 & oky1) ? (1.f - fx) * fy : 0.f;
            float w11 = (valid & okx1 & oky1) ? fx * fy : 0.f;

            int cx0 = min(max(x0, 0), WW - 1);
            int cx1 = min(max(x1, 0), WW - 1);
            int cy0 = min(max(y0, 0), HH - 1);
            int cy1 = min(max(y1, 0), HH - 1);

            int o00 = cy0 * WW + cx0;
            int o01 = cy0 * WW + cx1;
            int o10 = cy1 * WW + cx0;
            int o11 = cy1 * WW + cx1;

            float sumf = 0.f, ssq = 0.f, dot = 0.f;
#pragma unroll
            for (int c = 0; c < CC; c++) {
                const float* pc = sb + c * HWSZ;
                float f2 = w00 * pc[o00];
                f2 = fmaf(w01, pc[o01], f2);
                f2 = fmaf(w10, pc[o10], f2);
                f2 = fmaf(w11, pc[o11], f2);
                sumf += f2;
                ssq = fmaf(f2, f2, ssq);
                dot = fmaf(s_f1c[c * WW + tx], f2, dot);
            }
            float n2sq = fmaxf(ssq - sumf * sumf * (1.0f / CC), 0.f);
            float ncc = dot / (n1 * sqrtf(n2sq) + 1e-6f);
            cost[k] += ncc;
        }
    }

    const float invS = 1.0f / SS;
#pragma unroll
    for (int k = 0; k < DCH; k++) {
        int d = dch * DCH + k;
        out[((b * DD + d) * HH + h) * WW + tx] = cost[k] * invS;
    }
}

extern "C" void kernel_launch(void* const* d_in, const int* in_sizes, int n_in,
                              void* d_out, int out_size) {
    const float* ref_feats = (const float*)d_in[0];
    const float* src_feats = (const float*)d_in[1];
    const float* ref_intr = (const float*)d_in[2];
    const float* src_intr = (const float*)d_in[3];
    const float* ref_to_src = (const float*)d_in[4];
    const float* depths = (const float*)d_in[5];
    float* out = (float*)d_out;

    int npix = BB * HWSZ;
    prep_ref_kernel<<<(npix + 255) / 256, 256>>>(ref_feats);

    dim3 grid(NDCH, HH, BB);
    cost_kernel<<<grid, WW>>>(src_feats, ref_intr, src_intr, ref_to_src, depths, out);
}

// round 2
// speedup vs baseline: 1.1758x; 1.1758x over previous
#include <cuda_runtime.h>
#include <math.h>

// Problem constants (match reference setup_inputs)
#define BB 2
#define CC 16
#define CQ (CC / 4)     // channel quads
#define HH 160
#define WW 192
#define SS 3
#define DD 48
#define HWSZ (HH * WW)
#define DCH 8           // depths per block
#define NDCH (DD / DCH) // 6 depth chunks

// Scratch: centered ref features [B][C][H][W], per-pixel norm [B][H][W],
// and src features transposed to channel-quad layout [(s,b)][C/4][H*W] of float4
__device__ float g_f1c[BB * CC * HWSZ];
__device__ float g_n1[BB * HWSZ];
__device__ float4 g_srcq[SS * BB * CQ * HWSZ];

// ---------------------------------------------------------------------------
// Kernel 1: center ref feats over channel axis, store centered values + norm
// ---------------------------------------------------------------------------
__global__ void prep_ref_kernel(const float* __restrict__ ref) {
    int pix = blockIdx.x * blockDim.x + threadIdx.x;
    if (pix >= BB * HWSZ) return;
    int b = pix / HWSZ;
    int p = pix - b * HWSZ;

    float v[CC];
    float sum = 0.f;
#pragma unroll
    for (int c = 0; c < CC; c++) {
        v[c] = ref[(b * CC + c) * HWSZ + p];
        sum += v[c];
    }
    float m = sum * (1.0f / CC);
    float ss = 0.f;
#pragma unroll
    for (int c = 0; c < CC; c++) {
        float cv = v[c] - m;
        ss = fmaf(cv, cv, ss);
        g_f1c[(b * CC + c) * HWSZ + p] = cv;
    }
    g_n1[pix] = sqrtf(ss);
}

// ---------------------------------------------------------------------------
// Kernel 1b: transpose src [S,B,C,H,W] -> [(s,b), C/4, H*W] float4 (4 channels)
// ---------------------------------------------------------------------------
__global__ void prep_src_kernel(const float* __restrict__ src) {
    int idx = blockIdx.x * blockDim.x + threadIdx.x;
    if (idx >= SS * BB * CQ * HWSZ) return;
    int pix = idx % HWSZ;
    int t = idx / HWSZ;
    int q = t % CQ;
    int sb = t / CQ;

    const float* base = src + ((size_t)sb * CC + q * 4) * HWSZ + pix;
    float4 v;
    v.x = base[0 * HWSZ];
    v.y = base[1 * HWSZ];
    v.z = base[2 * HWSZ];
    v.w = base[3 * HWSZ];
    g_srcq[idx] = v;
}

// 3x3 inverse via adjugate
__device__ __forceinline__ void inv3x3(const float* K, float* I) {
    float a = K[0], b = K[1], c = K[2];
    float d = K[3], e = K[4], f = K[5];
    float g = K[6], h = K[7], i = K[8];
    float A = e * i - f * h;
    float Bm = -(d * i - f * g);
    float Cm = d * h - e * g;
    float det = a * A + b * Bm + c * Cm;
    float rd = 1.0f / det;
    I[0] = A * rd;
    I[1] = -(b * i - c * h) * rd;
    I[2] = (b * f - c * e) * rd;
    I[3] = Bm * rd;
    I[4] = (a * i - c * g) * rd;
    I[5] = -(a * f - c * d) * rd;
    I[6] = Cm * rd;
    I[7] = -(a * h - b * g) * rd;
    I[8] = (a * e - b * d) * rd;
}

__device__ __forceinline__ void mat3mul(const float* A, const float* B, float* C) {
#pragma unroll
    for (int i = 0; i < 3; i++)
#pragma unroll
        for (int j = 0; j < 3; j++)
            C[i * 3 + j] = A[i * 3 + 0] * B[0 * 3 + j] +
                           A[i * 3 + 1] * B[1 * 3 + j] +
                           A[i * 3 + 2] * B[2 * 3 + j];
}

// ---------------------------------------------------------------------------
// Kernel 2: cost volume. block = one image row (192 threads), one depth chunk.
// grid = (NDCH, H, B)
// ---------------------------------------------------------------------------
__global__ __launch_bounds__(WW, 5) void cost_kernel(
    const float* __restrict__ Kref,   // [B,3,3]
    const float* __restrict__ Ksrc,   // [S,B,3,3]
    const float* __restrict__ T,      // [S,B,4,4]
    const float* __restrict__ depths, // [D]
    float* __restrict__ out)          // [B,D,H,W]
{
    const int tx = threadIdx.x;          // w coordinate
    const int h = blockIdx.y;
    const int b = blockIdx.z;
    const int dch = blockIdx.x;
    const int pix = h * WW + tx;

    // centered ref features for this pixel -> registers (coalesced global loads)
    float f1c[CC];
#pragma unroll
    for (int c = 0; c < CC; c++)
        f1c[c] = g_f1c[(b * CC + c) * HWSZ + pix];
    const float n1 = g_n1[b * HWSZ + pix];

    // K^{-1} for this batch
    float Kinv[9];
    inv3x3(Kref + b * 9, Kinv);

    float dh[DCH];
#pragma unroll
    for (int k = 0; k < DCH; k++) dh[k] = depths[dch * DCH + k];

    float cost[DCH];
#pragma unroll
    for (int k = 0; k < DCH; k++) cost[k] = 0.f;

    const float u = (float)tx;
    const float v = (float)h;

    for (int s = 0; s < SS; s++) {
        // M = Ks * R * Kinv ; q = Ks * t
        const float* Tm = T + (s * BB + b) * 16;
        float R[9] = {Tm[0], Tm[1], Tm[2], Tm[4], Tm[5], Tm[6], Tm[8], Tm[9], Tm[10]};
        float t3[3] = {Tm[3], Tm[7], Tm[11]};
        const float* Ks = Ksrc + (s * BB + b) * 9;
        float RK[9], M[9];
        mat3mul(R, Kinv, RK);
        mat3mul(Ks, RK, M);
        float q0 = Ks[0] * t3[0] + Ks[1] * t3[1] + Ks[2] * t3[2];
        float q1 = Ks[3] * t3[0] + Ks[4] * t3[1] + Ks[5] * t3[2];
        float q2 = Ks[6] * t3[0] + Ks[7] * t3[1] + Ks[8] * t3[2];

        // per-pixel homogeneous ray through M (depth-independent part)
        float hp0 = M[0] * u + M[1] * v + M[2];
        float hp1 = M[3] * u + M[4] * v + M[5];
        float hp2 = M[6] * u + M[7] * v + M[8];

        const float4* sb4 = g_srcq + (size_t)(s * BB + b) * CQ * HWSZ;

        for (int k = 0; k < DCH; k++) {
            float d = dh[k];
            float p0 = fmaf(d, hp0, q0);
            float p1 = fmaf(d, hp1, q1);
            float p2 = fmaf(d, hp2, q2);

            bool valid = p2 > 0.001f;
            float zs = fmaxf(p2, 0.001f);
            float inz = 1.0f / zs;
            float x = p0 * inz;
            float y = p1 * inz;

            float x0f = floorf(x);
            float y0f = floorf(y);
            float fx = x - x0f;
            float fy = y - y0f;
            int x0 = (int)x0f;
            int y0 = (int)y0f;
            int x1 = x0 + 1;
            int y1 = y0 + 1;

            bool okx0 = (x0 >= 0) & (x0 < WW);
            bool okx1 = (x1 >= 0) & (x1 < WW);
            bool oky0 = (y0 >= 0) & (y0 < HH);
            bool oky1 = (y1 >= 0) & (y1 < HH);

            float w00 = (valid & okx0 & oky0) ? (1.f - fx) * (1.f - fy) : 0.f;
            float w01 = (valid & okx1 & oky0) ? fx * (1.f - fy) : 0.f;
            float w10 = (valid & okx0 & oky1) ? (1.f - fx) * fy : 0.f;
            float w11 = (valid & okx1 & oky1) ? fx * fy : 0.f;

            int cx0 = min(max(x0, 0), WW - 1);
            int cx1 = min(max(x1, 0), WW - 1);
            int cy0 = min(max(y0, 0), HH - 1);
            int cy1 = min(max(y1, 0), HH - 1);

            int o00 = cy0 * WW + cx0;
            int o01 = cy0 * WW + cx1;
            int o10 = cy1 * WW + cx0;
            int o11 = cy1 * WW + cx1;

            float sumf = 0.f, ssq = 0.f, dot = 0.f;
#pragma unroll
            for (int q = 0; q < CQ; q++) {
                const float4* pq = sb4 + q * HWSZ;
                float4 a00 = pq[o00];
                float4 a01 = pq[o01];
                float4 a10 = pq[o10];
                float4 a11 = pq[o11];

                float f2x = w00 * a00.x;
                float f2y = w00 * a00.y;
                float f2z = w00 * a00.z;
                float f2w = w00 * a00.w;
                f2x = fmaf(w01, a01.x, f2x);
                f2y = fmaf(w01, a01.y, f2y);
                f2z = fmaf(w01, a01.z, f2z);
                f2w = fmaf(w01, a01.w, f2w);
                f2x = fmaf(w10, a10.x, f2x);
                f2y = fmaf(w10, a10.y, f2y);
                f2z = fmaf(w10, a10.z, f2z);
                f2w = fmaf(w10, a10.w, f2w);
                f2x = fmaf(w11, a11.x, f2x);
                f2y = fmaf(w11, a11.y, f2y);
                f2z = fmaf(w11, a11.z, f2z);
                f2w = fmaf(w11, a11.w, f2w);

                sumf += f2x + f2y + f2z + f2w;
                ssq = fmaf(f2x, f2x, ssq);
                ssq = fmaf(f2y, f2y, ssq);
                ssq = fmaf(f2z, f2z, ssq);
                ssq = fmaf(f2w, f2w, ssq);
                dot = fmaf(f1c[q * 4 + 0], f2x, dot);
                dot = fmaf(f1c[q * 4 + 1], f2y, dot);
                dot = fmaf(f1c[q * 4 + 2], f2z, dot);
                dot = fmaf(f1c[q * 4 + 3], f2w, dot);
            }
            float n2sq = fmaxf(ssq - sumf * sumf * (1.0f / CC), 0.f);
            float ncc = dot / (n1 * sqrtf(n2sq) + 1e-6f);
            cost[k] += ncc;
        }
    }

    const float invS = 1.0f / SS;
#pragma unroll
    for (int k = 0; k < DCH; k++) {
        int d = dch * DCH + k;
        out[((b * DD + d) * HH + h) * WW + tx] = cost[k] * invS;
    }
}

extern "C" void kernel_launch(void* const* d_in, const int* in_sizes, int n_in,
                              void* d_out, int out_size) {
    const float* ref_feats = (const float*)d_in[0];
    const float* src_feats = (const float*)d_in[1];
    const float* ref_intr = (const float*)d_in[2];
    const float* src_intr = (const float*)d_in[3];
    const float* ref_to_src = (const float*)d_in[4];
    const float* depths = (const float*)d_in[5];
    float* out = (float*)d_out;

    int npix = BB * HWSZ;
    prep_ref_kernel<<<(npix + 255) / 256, 256>>>(ref_feats);

    int nq = SS * BB * CQ * HWSZ;
    prep_src_kernel<<<(nq + 255) / 256, 256>>>(src_feats);

    dim3 grid(NDCH, HH, BB);
    cost_kernel<<<grid, WW>>>(ref_intr, src_intr, ref_to_src, depths, out);
}

// round 3
// speedup vs baseline: 1.3831x; 1.1763x over previous
#include <cuda_runtime.h>
#include <math.h>

// Problem constants (match reference setup_inputs)
#define BB 2
#define CC 16
#define CQ (CC / 4)     // channel quads
#define HH 160
#define WW 192
#define SS 3
#define DD 48
#define HWSZ (HH * WW)
#define DCH 8           // depths per block
#define NDCH (DD / DCH) // 6 depth chunks

// Packed f32x2 helpers (Blackwell sm_103a)
#define FMA2(d, a, b, c) asm("fma.rn.f32x2 %0, %1, %2, %3;" : "=l"(d) : "l"(a), "l"(b), "l"(c))
#define MUL2(d, a, b)    asm("mul.rn.f32x2 %0, %1, %2;"     : "=l"(d) : "l"(a), "l"(b))
#define ADD2(d, a, b)    asm("add.rn.f32x2 %0, %1, %2;"     : "=l"(d) : "l"(a), "l"(b))
#define PACK2(d, lo, hi) asm("mov.b64 %0, {%1, %2};" : "=l"(d) : "r"(lo), "r"(hi))
#define UNPACK2(lo, hi, s) asm("mov.b64 {%0, %1}, %2;" : "=r"(lo), "=r"(hi) : "l"(s))

typedef unsigned long long u64;

// Scratch: centered ref features [B][C][H][W], per-pixel norm [B][H][W],
// and src features transposed to channel-quad layout [(s,b)][C/4][H*W] of float4
__device__ float g_f1c[BB * CC * HWSZ];
__device__ float g_n1[BB * HWSZ];
__device__ float4 g_srcq[SS * BB * CQ * HWSZ];

// ---------------------------------------------------------------------------
// Kernel 1: center ref feats over channel axis, store centered values + norm
// ---------------------------------------------------------------------------
__global__ void prep_ref_kernel(const float* __restrict__ ref) {
    int pix = blockIdx.x * blockDim.x + threadIdx.x;
    if (pix >= BB * HWSZ) return;
    int b = pix / HWSZ;
    int p = pix - b * HWSZ;

    float v[CC];
    float sum = 0.f;
#pragma unroll
    for (int c = 0; c < CC; c++) {
        v[c] = ref[(b * CC + c) * HWSZ + p];
        sum += v[c];
    }
    float m = sum * (1.0f / CC);
    float ss = 0.f;
#pragma unroll
    for (int c = 0; c < CC; c++) {
        float cv = v[c] - m;
        ss = fmaf(cv, cv, ss);
        g_f1c[(b * CC + c) * HWSZ + p] = cv;
    }
    g_n1[pix] = sqrtf(ss);
}

// ---------------------------------------------------------------------------
// Kernel 1b: transpose src [S,B,C,H,W] -> [(s,b), C/4, H*W] float4 (4 channels)
// ---------------------------------------------------------------------------
__global__ void prep_src_kernel(const float* __restrict__ src) {
    int idx = blockIdx.x * blockDim.x + threadIdx.x;
    if (idx >= SS * BB * CQ * HWSZ) return;
    int pix = idx % HWSZ;
    int t = idx / HWSZ;
    int q = t % CQ;
    int sb = t / CQ;

    const float* base = src + ((size_t)sb * CC + q * 4) * HWSZ + pix;
    float4 v;
    v.x = base[0 * HWSZ];
    v.y = base[1 * HWSZ];
    v.z = base[2 * HWSZ];
    v.w = base[3 * HWSZ];
    g_srcq[idx] = v;
}

// 3x3 inverse via adjugate
__device__ __forceinline__ void inv3x3(const float* K, float* I) {
    float a = K[0], b = K[1], c = K[2];
    float d = K[3], e = K[4], f = K[5];
    float g = K[6], h = K[7], i = K[8];
    float A = e * i - f * h;
    float Bm = -(d * i - f * g);
    float Cm = d * h - e * g;
    float det = a * A + b * Bm + c * Cm;
    float rd = 1.0f / det;
    I[0] = A * rd;
    I[1] = -(b * i - c * h) * rd;
    I[2] = (b * f - c * e) * rd;
    I[3] = Bm * rd;
    I[4] = (a * i - c * g) * rd;
    I[5] = -(a * f - c * d) * rd;
    I[6] = Cm * rd;
    I[7] = -(a * h - b * g) * rd;
    I[8] = (a * e - b * d) * rd;
}

__device__ __forceinline__ void mat3mul(const float* A, const float* B, float* C) {
#pragma unroll
    for (int i = 0; i < 3; i++)
#pragma unroll
        for (int j = 0; j < 3; j++)
            C[i * 3 + j] = A[i * 3 + 0] * B[0 * 3 + j] +
                           A[i * 3 + 1] * B[1 * 3 + j] +
                           A[i * 3 + 2] * B[2 * 3 + j];
}

// ---------------------------------------------------------------------------
// Kernel 2: cost volume. block = one image row (192 threads), one depth chunk.
// grid = (NDCH, H, B)
// ---------------------------------------------------------------------------
__global__ __launch_bounds__(WW, 4) void cost_kernel(
    const float* __restrict__ Kref,   // [B,3,3]
    const float* __restrict__ Ksrc,   // [S,B,3,3]
    const float* __restrict__ T,      // [S,B,4,4]
    const float* __restrict__ depths, // [D]
    float* __restrict__ out)          // [B,D,H,W]
{
    const int tx = threadIdx.x;          // w coordinate
    const int h = blockIdx.y;
    const int b = blockIdx.z;
    const int dch = blockIdx.x;
    const int pix = h * WW + tx;

    // centered ref features for this pixel -> packed f32x2 register pairs
    u64 f1p[CC / 2];
#pragma unroll
    for (int j = 0; j < CC / 2; j++) {
        float lo = g_f1c[(b * CC + 2 * j + 0) * HWSZ + pix];
        float hi = g_f1c[(b * CC + 2 * j + 1) * HWSZ + pix];
        PACK2(f1p[j], __float_as_uint(lo), __float_as_uint(hi));
    }
    const float n1 = g_n1[b * HWSZ + pix];

    // K^{-1} for this batch
    float Kinv[9];
    inv3x3(Kref + b * 9, Kinv);

    float dh[DCH];
#pragma unroll
    for (int k = 0; k < DCH; k++) dh[k] = depths[dch * DCH + k];

    float cost[DCH];
#pragma unroll
    for (int k = 0; k < DCH; k++) cost[k] = 0.f;

    const float u = (float)tx;
    const float v = (float)h;

    for (int s = 0; s < SS; s++) {
        // M = Ks * R * Kinv ; q = Ks * t
        const float* Tm = T + (s * BB + b) * 16;
        float R[9] = {Tm[0], Tm[1], Tm[2], Tm[4], Tm[5], Tm[6], Tm[8], Tm[9], Tm[10]};
        float t3[3] = {Tm[3], Tm[7], Tm[11]};
        const float* Ks = Ksrc + (s * BB + b) * 9;
        float RK[9], M[9];
        mat3mul(R, Kinv, RK);
        mat3mul(Ks, RK, M);
        float q0 = Ks[0] * t3[0] + Ks[1] * t3[1] + Ks[2] * t3[2];
        float q1 = Ks[3] * t3[0] + Ks[4] * t3[1] + Ks[5] * t3[2];
        float q2 = Ks[6] * t3[0] + Ks[7] * t3[1] + Ks[8] * t3[2];

        // per-pixel homogeneous ray through M (depth-independent part)
        float hp0 = M[0] * u + M[1] * v + M[2];
        float hp1 = M[3] * u + M[4] * v + M[5];
        float hp2 = M[6] * u + M[7] * v + M[8];

        const ulonglong2* sb2 =
            reinterpret_cast<const ulonglong2*>(g_srcq) + (size_t)(s * BB + b) * CQ * HWSZ;

        for (int k = 0; k < DCH; k++) {
            float d = dh[k];
            float p0 = fmaf(d, hp0, q0);
            float p1 = fmaf(d, hp1, q1);
            float p2 = fmaf(d, hp2, q2);

            bool valid = p2 > 0.001f;
            float zs = fmaxf(p2, 0.001f);
            float inz = 1.0f / zs;
            float x = p0 * inz;
            float y = p1 * inz;

            float x0f = floorf(x);
            float y0f = floorf(y);
            float fx = x - x0f;
            float fy = y - y0f;
            int x0 = (int)x0f;
            int y0 = (int)y0f;
            int x1 = x0 + 1;
            int y1 = y0 + 1;

            bool okx0 = (x0 >= 0) & (x0 < WW);
            bool okx1 = (x1 >= 0) & (x1 < WW);
            bool oky0 = (y0 >= 0) & (y0 < HH);
            bool oky1 = (y1 >= 0) & (y1 < HH);

            float w00 = (valid & okx0 & oky0) ? (1.f - fx) * (1.f - fy) : 0.f;
            float w01 = (valid & okx1 & oky0) ? fx * (1.f - fy) : 0.f;
            float w10 = (valid & okx0 & oky1) ? (1.f - fx) * fy : 0.f;
            float w11 = (valid & okx1 & oky1) ? fx * fy : 0.f;

            int cx0 = min(max(x0, 0), WW - 1);
            int cx1 = min(max(x1, 0), WW - 1);
            int cy0 = min(max(y0, 0), HH - 1);
            int cy1 = min(max(y1, 0), HH - 1);

            int o00 = cy0 * WW + cx0;
            int o01 = cy0 * WW + cx1;
            int o10 = cy1 * WW + cx0;
            int o11 = cy1 * WW + cx1;

            // broadcast weights into f32x2 pairs
            u64 w00p, w01p, w10p, w11p;
            {
                unsigned int w;
                w = __float_as_uint(w00); PACK2(w00p, w, w);
                w = __float_as_uint(w01); PACK2(w01p, w, w);
                w = __float_as_uint(w10); PACK2(w10p, w, w);
                w = __float_as_uint(w11); PACK2(w11p, w, w);
            }

            u64 sum2 = 0, ssq2 = 0, dot2 = 0;
#pragma unroll
            for (int q = 0; q < CQ; q++) {
                const ulonglong2* pq = sb2 + q * HWSZ;
                ulonglong2 a00 = pq[o00];
                ulonglong2 a01 = pq[o01];
                ulonglong2 a10 = pq[o10];
                ulonglong2 a11 = pq[o11];

                u64 f2l, f2h;
                MUL2(f2l, w00p, a00.x);
                FMA2(f2l, w01p, a01.x, f2l);
                FMA2(f2l, w10p, a10.x, f2l);
                FMA2(f2l, w11p, a11.x, f2l);
                MUL2(f2h, w00p, a00.y);
                FMA2(f2h, w01p, a01.y, f2h);
                FMA2(f2h, w10p, a10.y, f2h);
                FMA2(f2h, w11p, a11.y, f2h);

                ADD2(sum2, sum2, f2l);
                ADD2(sum2, sum2, f2h);
                FMA2(ssq2, f2l, f2l, ssq2);
                FMA2(ssq2, f2h, f2h, ssq2);
                FMA2(dot2, f1p[2 * q + 0], f2l, dot2);
                FMA2(dot2, f1p[2 * q + 1], f2h, dot2);
            }

            unsigned int lo, hi;
            UNPACK2(lo, hi, sum2);
            float sumf = __uint_as_float(lo) + __uint_as_float(hi);
            UNPACK2(lo, hi, ssq2);
            float ssq = __uint_as_float(lo) + __uint_as_float(hi);
            UNPACK2(lo, hi, dot2);
            float dot = __uint_as_float(lo) + __uint_as_float(hi);

            float n2sq = fmaxf(ssq - sumf * sumf * (1.0f / CC), 0.f);
            float ncc = dot / (n1 * sqrtf(n2sq) + 1e-6f);
            cost[k] += ncc;
        }
    }

    const float invS = 1.0f / SS;
#pragma unroll
    for (int k = 0; k < DCH; k++) {
        int d = dch * DCH + k;
        out[((b * DD + d) * HH + h) * WW + tx] = cost[k] * invS;
    }
}

extern "C" void kernel_launch(void* const* d_in, const int* in_sizes, int n_in,
                              void* d_out, int out_size) {
    const float* ref_feats = (const float*)d_in[0];
    const float* src_feats = (const float*)d_in[1];
    const float* ref_intr = (const float*)d_in[2];
    const float* src_intr = (const float*)d_in[3];
    const float* ref_to_src = (const float*)d_in[4];
    const float* depths = (const float*)d_in[5];
    float* out = (float*)d_out;

    int npix = BB * HWSZ;
    prep_ref_kernel<<<(npix + 255) / 256, 256>>>(ref_feats);

    int nq = SS * BB * CQ * HWSZ;
    prep_src_kernel<<<(nq + 255) / 256, 256>>>(src_feats);

    dim3 grid(NDCH, HH, BB);
    cost_kernel<<<grid, WW>>>(ref_intr, src_intr, ref_to_src, depths, out);
}

// round 4
// speedup vs baseline: 1.4709x; 1.0635x over previous
#include <cuda_runtime.h>
#include <cuda_fp16.h>
#include <math.h>

// Problem constants (match reference setup_inputs)
#define BB 2
#define CC 16
#define CQ (CC / 4)     // channel quads
#define HH 160
#define WW 192
#define SS 3
#define DD 48
#define HWSZ (HH * WW)
#define DCH 6           // depths per block
#define NDCH (DD / DCH) // 8 depth chunks
#define PIXBLK 256
#define NPB (HWSZ / PIXBLK) // 120 pixel-blocks per image

// Packed f32x2 helpers (Blackwell sm_103a)
#define FMA2(d, a, b, c) asm("fma.rn.f32x2 %0, %1, %2, %3;" : "=l"(d) : "l"(a), "l"(b), "l"(c))
#define MUL2(d, a, b)    asm("mul.rn.f32x2 %0, %1, %2;"     : "=l"(d) : "l"(a), "l"(b))
#define ADD2(d, a, b)    asm("add.rn.f32x2 %0, %1, %2;"     : "=l"(d) : "l"(a), "l"(b))
#define PACK2(d, lo, hi) asm("mov.b64 %0, {%1, %2};" : "=l"(d) : "r"(lo), "r"(hi))
#define UNPACK2(lo, hi, s) asm("mov.b64 {%0, %1}, %2;" : "=r"(lo), "=r"(hi) : "l"(s))

typedef unsigned long long u64;

// Scratch: centered ref features [B][C][H][W], per-pixel norm [B][H][W],
// and src features transposed to fp16 channel-quad layout:
// [(s,b)][C/4][H*W] of uint2 (4 halves)
__device__ float g_f1c[BB * CC * HWSZ];
__device__ float g_n1[BB * HWSZ];
__device__ uint2 g_srch[SS * BB * CQ * HWSZ];

#define REF_BLOCKS ((BB * HWSZ) / 256)                    // 240
#define SRC_BLOCKS ((SS * BB * CQ * HWSZ) / 256)          // 2880

// ---------------------------------------------------------------------------
// Fused prep: blocks [0,REF_BLOCKS) center ref feats; rest transpose src->fp16
// ---------------------------------------------------------------------------
__global__ void prep_kernel(const float* __restrict__ ref,
                            const float* __restrict__ src) {
    if (blockIdx.x < REF_BLOCKS) {
        int pix = blockIdx.x * 256 + threadIdx.x;
        int b = pix / HWSZ;
        int p = pix - b * HWSZ;

        float v[CC];
        float sum = 0.f;
#pragma unroll
        for (int c = 0; c < CC; c++) {
            v[c] = ref[(b * CC + c) * HWSZ + p];
            sum += v[c];
        }
        float m = sum * (1.0f / CC);
        float ss = 0.f;
#pragma unroll
        for (int c = 0; c < CC; c++) {
            float cv = v[c] - m;
            ss = fmaf(cv, cv, ss);
            g_f1c[(b * CC + c) * HWSZ + p] = cv;
        }
        g_n1[pix] = sqrtf(ss);
    } else {
        int idx = (blockIdx.x - REF_BLOCKS) * 256 + threadIdx.x;
        int pix = idx % HWSZ;
        int t = idx / HWSZ;
        int q = t % CQ;
        int sb = t / CQ;

        const float* base = src + ((size_t)sb * CC + q * 4) * HWSZ + pix;
        __half2 h0 = __floats2half2_rn(base[0 * HWSZ], base[1 * HWSZ]);
        __half2 h1 = __floats2half2_rn(base[2 * HWSZ], base[3 * HWSZ]);
        uint2 v;
        v.x = *reinterpret_cast<unsigned int*>(&h0);
        v.y = *reinterpret_cast<unsigned int*>(&h1);
        g_srch[idx] = v;
    }
}

// fp16x2 -> packed f32x2 (u64)
__device__ __forceinline__ u64 h2f2(unsigned int h) {
    __half2 hh = *reinterpret_cast<const __half2*>(&h);
    float2 f = __half22float2(hh);
    u64 r;
    PACK2(r, __float_as_uint(f.x), __float_as_uint(f.y));
    return r;
}

// 3x3 inverse via adjugate
__device__ __forceinline__ void inv3x3(const float* K, float* I) {
    float a = K[0], b = K[1], c = K[2];
    float d = K[3], e = K[4], f = K[5];
    float g = K[6], h = K[7], i = K[8];
    float A = e * i - f * h;
    float Bm = -(d * i - f * g);
    float Cm = d * h - e * g;
    float det = a * A + b * Bm + c * Cm;
    float rd = 1.0f / det;
    I[0] = A * rd;
    I[1] = -(b * i - c * h) * rd;
    I[2] = (b * f - c * e) * rd;
    I[3] = Bm * rd;
    I[4] = (a * i - c * g) * rd;
    I[5] = -(a * f - c * d) * rd;
    I[6] = Cm * rd;
    I[7] = -(a * h - b * g) * rd;
    I[8] = (a * e - b * d) * rd;
}

__device__ __forceinline__ void mat3mul(const float* A, const float* B, float* C) {
#pragma unroll
    for (int i = 0; i < 3; i++)
#pragma unroll
        for (int j = 0; j < 3; j++)
            C[i * 3 + j] = A[i * 3 + 0] * B[0 * 3 + j] +
                           A[i * 3 + 1] * B[1 * 3 + j] +
                           A[i * 3 + 2] * B[2 * 3 + j];
}

// ---------------------------------------------------------------------------
// Kernel 2: cost volume. block = 256 consecutive pixels, one depth chunk.
// grid = (NPB, NDCH, B)
// ---------------------------------------------------------------------------
__global__ __launch_bounds__(PIXBLK, 4) void cost_kernel(
    const float* __restrict__ Kref,   // [B,3,3]
    const float* __restrict__ Ksrc,   // [S,B,3,3]
    const float* __restrict__ T,      // [S,B,4,4]
    const float* __restrict__ depths, // [D]
    float* __restrict__ out)          // [B,D,H,W]
{
    const int pix = blockIdx.x * PIXBLK + threadIdx.x;
    const int b = blockIdx.z;
    const int dch = blockIdx.y;
    const int hrow = pix / WW;
    const int wcol = pix - hrow * WW;

    // centered ref features for this pixel -> packed f32x2 register pairs
    u64 f1p[CC / 2];
#pragma unroll
    for (int j = 0; j < CC / 2; j++) {
        float lo = g_f1c[(b * CC + 2 * j + 0) * HWSZ + pix];
        float hi = g_f1c[(b * CC + 2 * j + 1) * HWSZ + pix];
        PACK2(f1p[j], __float_as_uint(lo), __float_as_uint(hi));
    }
    const float n1 = g_n1[b * HWSZ + pix];

    // K^{-1} for this batch
    float Kinv[9];
    inv3x3(Kref + b * 9, Kinv);

    float dh[DCH];
#pragma unroll
    for (int k = 0; k < DCH; k++) dh[k] = depths[dch * DCH + k];

    float cost[DCH];
#pragma unroll
    for (int k = 0; k < DCH; k++) cost[k] = 0.f;

    const float u = (float)wcol;
    const float v = (float)hrow;

    for (int s = 0; s < SS; s++) {
        // M = Ks * R * Kinv ; q = Ks * t
        const float* Tm = T + (s * BB + b) * 16;
        float R[9] = {Tm[0], Tm[1], Tm[2], Tm[4], Tm[5], Tm[6], Tm[8], Tm[9], Tm[10]};
        float t3[3] = {Tm[3], Tm[7], Tm[11]};
        const float* Ks = Ksrc + (s * BB + b) * 9;
        float RK[9], M[9];
        mat3mul(R, Kinv, RK);
        mat3mul(Ks, RK, M);
        float q0 = Ks[0] * t3[0] + Ks[1] * t3[1] + Ks[2] * t3[2];
        float q1 = Ks[3] * t3[0] + Ks[4] * t3[1] + Ks[5] * t3[2];
        float q2 = Ks[6] * t3[0] + Ks[7] * t3[1] + Ks[8] * t3[2];

        // per-pixel homogeneous ray through M (depth-independent part)
        float hp0 = M[0] * u + M[1] * v + M[2];
        float hp1 = M[3] * u + M[4] * v + M[5];
        float hp2 = M[6] * u + M[7] * v + M[8];

        const uint2* sb2 = g_srch + (size_t)(s * BB + b) * CQ * HWSZ;

        for (int k = 0; k < DCH; k++) {
            float d = dh[k];
            float p0 = fmaf(d, hp0, q0);
            float p1 = fmaf(d, hp1, q1);
            float p2 = fmaf(d, hp2, q2);

            bool valid = p2 > 0.001f;
            float zs = fmaxf(p2, 0.001f);
            float inz = 1.0f / zs;
            float x = p0 * inz;
            float y = p1 * inz;

            float x0f = floorf(x);
            float y0f = floorf(y);
            float fx = x - x0f;
            float fy = y - y0f;
            int x0 = (int)x0f;
            int y0 = (int)y0f;
            int x1 = x0 + 1;
            int y1 = y0 + 1;

            bool okx0 = (x0 >= 0) & (x0 < WW);
            bool okx1 = (x1 >= 0) & (x1 < WW);
            bool oky0 = (y0 >= 0) & (y0 < HH);
            bool oky1 = (y1 >= 0) & (y1 < HH);

            float w00 = (valid & okx0 & oky0) ? (1.f - fx) * (1.f - fy) : 0.f;
            float w01 = (valid & okx1 & oky0) ? fx * (1.f - fy) : 0.f;
            float w10 = (valid & okx0 & oky1) ? (1.f - fx) * fy : 0.f;
            float w11 = (valid & okx1 & oky1) ? fx * fy : 0.f;

            int cx0 = min(max(x0, 0), WW - 1);
            int cx1 = min(max(x1, 0), WW - 1);
            int cy0 = min(max(y0, 0), HH - 1);
            int cy1 = min(max(y1, 0), HH - 1);

            int o00 = cy0 * WW + cx0;
            int o01 = cy0 * WW + cx1;
            int o10 = cy1 * WW + cx0;
            int o11 = cy1 * WW + cx1;

            // broadcast weights into f32x2 pairs
            u64 w00p, w01p, w10p, w11p;
            {
                unsigned int w;
                w = __float_as_uint(w00); PACK2(w00p, w, w);
                w = __float_as_uint(w01); PACK2(w01p, w, w);
                w = __float_as_uint(w10); PACK2(w10p, w, w);
                w = __float_as_uint(w11); PACK2(w11p, w, w);
            }

            u64 sum2 = 0, ssq2 = 0, dot2 = 0;
#pragma unroll
            for (int q = 0; q < CQ; q++) {
                const uint2* pq = sb2 + q * HWSZ;
                uint2 a00 = pq[o00];
                uint2 a01 = pq[o01];
                uint2 a10 = pq[o10];
                uint2 a11 = pq[o11];

                u64 f2l, f2h;
                MUL2(f2l, w00p, h2f2(a00.x));
                FMA2(f2l, w01p, h2f2(a01.x), f2l);
                FMA2(f2l, w10p, h2f2(a10.x), f2l);
                FMA2(f2l, w11p, h2f2(a11.x), f2l);
                MUL2(f2h, w00p, h2f2(a00.y));
                FMA2(f2h, w01p, h2f2(a01.y), f2h);
                FMA2(f2h, w10p, h2f2(a10.y), f2h);
                FMA2(f2h, w11p, h2f2(a11.y), f2h);

                ADD2(sum2, sum2, f2l);
                ADD2(sum2, sum2, f2h);
                FMA2(ssq2, f2l, f2l, ssq2);
                FMA2(ssq2, f2h, f2h, ssq2);
                FMA2(dot2, f1p[2 * q + 0], f2l, dot2);
                FMA2(dot2, f1p[2 * q + 1], f2h, dot2);
            }

            unsigned int lo, hi;
            UNPACK2(lo, hi, sum2);
            float sumf = __uint_as_float(lo) + __uint_as_float(hi);
            UNPACK2(lo, hi, ssq2);
            float ssq = __uint_as_float(lo) + __uint_as_float(hi);
            UNPACK2(lo, hi, dot2);
            float dot = __uint_as_float(lo) + __uint_as_float(hi);

            float n2sq = fmaxf(ssq - sumf * sumf * (1.0f / CC), 0.f);
            float den = fmaf(n1, sqrtf(n2sq), 1e-6f);
            cost[k] += __fdividef(dot, den);
        }
    }

    const float invS = 1.0f / SS;
#pragma unroll
    for (int k = 0; k < DCH; k++) {
        int d = dch * DCH + k;
        out[(b * DD + d) * HWSZ + pix] = cost[k] * invS;
    }
}

extern "C" void kernel_launch(void* const* d_in, const int* in_sizes, int n_in,
                              void* d_out, int out_size) {
    const float* ref_feats = (const float*)d_in[0];
    const float* src_feats = (const float*)d_in[1];
    const float* ref_intr = (const float*)d_in[2];
    const float* src_intr = (const float*)d_in[3];
    const float* ref_to_src = (const float*)d_in[4];
    const float* depths = (const float*)d_in[5];
    float* out = (float*)d_out;

    prep_kernel<<<REF_BLOCKS + SRC_BLOCKS, 256>>>(ref_feats, src_feats);

    dim3 grid(NPB, NDCH, BB);
    cost_kernel<<<grid, PIXBLK>>>(ref_intr, src_intr, ref_to_src, depths, out);
}

// round 5
// speedup vs baseline: 1.7577x; 1.1950x over previous
#include <cuda_runtime.h>
#include <cuda_fp16.h>
#include <math.h>

// Problem constants (match reference setup_inputs)
#define BB 2
#define CC 16
#define HH 160
#define WW 192
#define SS 3
#define DD 48
#define HWSZ (HH * WW)
#define DCH 6           // depths per block
#define NDCH (DD / DCH) // 8 depth chunks
#define PIXBLK 256
#define NPB (HWSZ / PIXBLK) // 120 pixel-blocks per image

// Packed f32x2 helpers (Blackwell sm_103a)
#define FMA2(d, a, b, c) asm("fma.rn.f32x2 %0, %1, %2, %3;" : "=l"(d) : "l"(a), "l"(b), "l"(c))
#define ADD2(d, a, b)    asm("add.rn.f32x2 %0, %1, %2;"     : "=l"(d) : "l"(a), "l"(b))
#define PACK2(d, lo, hi) asm("mov.b64 %0, {%1, %2};" : "=l"(d) : "r"(lo), "r"(hi))
#define UNPACK2(lo, hi, s) asm("mov.b64 {%0, %1}, %2;" : "=r"(lo), "=r"(hi) : "l"(s))

typedef unsigned long long u64;

// Scratch: centered ref features [B][C][H][W], per-pixel norm [B][H][W],
// and src features in AoS fp16 layout: [sb][pix] -> 16 channels (32 bytes)
__device__ float g_f1c[BB * CC * HWSZ];
__device__ float g_n1[BB * HWSZ];
__device__ uint4 g_srcv[SS * BB * HWSZ * 2]; // 2 x uint4 per pixel

#define REF_BLOCKS ((BB * HWSZ) / 256)        // 240
#define SRC_BLOCKS ((SS * BB * HWSZ) / 256)   // 720

// ---------------------------------------------------------------------------
// Fused prep: blocks [0,REF_BLOCKS) center ref feats; rest transpose src->fp16 AoS
// ---------------------------------------------------------------------------
__global__ void prep_kernel(const float* __restrict__ ref,
                            const float* __restrict__ src) {
    if (blockIdx.x < REF_BLOCKS) {
        int pix = blockIdx.x * 256 + threadIdx.x;
        int b = pix / HWSZ;
        int p = pix - b * HWSZ;

        float v[CC];
        float sum = 0.f;
#pragma unroll
        for (int c = 0; c < CC; c++) {
            v[c] = ref[(b * CC + c) * HWSZ + p];
            sum += v[c];
        }
        float m = sum * (1.0f / CC);
        float ss = 0.f;
#pragma unroll
        for (int c = 0; c < CC; c++) {
            float cv = v[c] - m;
            ss = fmaf(cv, cv, ss);
            g_f1c[(b * CC + c) * HWSZ + p] = cv;
        }
        g_n1[pix] = sqrtf(ss);
    } else {
        int idx = (blockIdx.x - REF_BLOCKS) * 256 + threadIdx.x; // sb*HWSZ + pix
        int pix = idx % HWSZ;
        int sb = idx / HWSZ;

        const float* base = src + (size_t)sb * CC * HWSZ + pix;
        unsigned int h[8];
#pragma unroll
        for (int j = 0; j < 8; j++) {
            __half2 hh = __floats2half2_rn(base[(2 * j) * HWSZ], base[(2 * j + 1) * HWSZ]);
            h[j] = *reinterpret_cast<unsigned int*>(&hh);
        }
        uint4 a = make_uint4(h[0], h[1], h[2], h[3]);
        uint4 bq = make_uint4(h[4], h[5], h[6], h[7]);
        g_srcv[idx * 2 + 0] = a;
        g_srcv[idx * 2 + 1] = bq;
    }
}

__device__ __forceinline__ __half2 u2h2(unsigned int u) {
    return *reinterpret_cast<const __half2*>(&u);
}

// 3x3 inverse via adjugate
__device__ __forceinline__ void inv3x3(const float* K, float* I) {
    float a = K[0], b = K[1], c = K[2];
    float d = K[3], e = K[4], f = K[5];
    float g = K[6], h = K[7], i = K[8];
    float A = e * i - f * h;
    float Bm = -(d * i - f * g);
    float Cm = d * h - e * g;
    float det = a * A + b * Bm + c * Cm;
    float rd = 1.0f / det;
    I[0] = A * rd;
    I[1] = -(b * i - c * h) * rd;
    I[2] = (b * f - c * e) * rd;
    I[3] = Bm * rd;
    I[4] = (a * i - c * g) * rd;
    I[5] = -(a * f - c * d) * rd;
    I[6] = Cm * rd;
    I[7] = -(a * h - b * g) * rd;
    I[8] = (a * e - b * d) * rd;
}

__device__ __forceinline__ void mat3mul(const float* A, const float* B, float* C) {
#pragma unroll
    for (int i = 0; i < 3; i++)
#pragma unroll
        for (int j = 0; j < 3; j++)
            C[i * 3 + j] = A[i * 3 + 0] * B[0 * 3 + j] +
                           A[i * 3 + 1] * B[1 * 3 + j] +
                           A[i * 3 + 2] * B[2 * 3 + j];
}

// process 4 half2 lanes (one uint4 per corner): blend in fp16, accumulate fp32
__device__ __forceinline__ void blend_accum4(
    uint4 a00, uint4 a01, uint4 a10, uint4 a11,
    __half2 w00h, __half2 w01h, __half2 w10h, __half2 w11h,
    const u64* f1p, u64& sum2, u64& ssq2, u64& dot2)
{
    const unsigned int* p00 = reinterpret_cast<const unsigned int*>(&a00);
    const unsigned int* p01 = reinterpret_cast<const unsigned int*>(&a01);
    const unsigned int* p10 = reinterpret_cast<const unsigned int*>(&a10);
    const unsigned int* p11 = reinterpret_cast<const unsigned int*>(&a11);
#pragma unroll
    for (int j = 0; j < 4; j++) {
        __half2 f2h = __hmul2(w00h, u2h2(p00[j]));
        f2h = __hfma2(w01h, u2h2(p01[j]), f2h);
        f2h = __hfma2(w10h, u2h2(p10[j]), f2h);
        f2h = __hfma2(w11h, u2h2(p11[j]), f2h);
        float2 ff = __half22float2(f2h);
        u64 f2p;
        PACK2(f2p, __float_as_uint(ff.x), __float_as_uint(ff.y));
        ADD2(sum2, sum2, f2p);
        FMA2(ssq2, f2p, f2p, ssq2);
        FMA2(dot2, f1p[j], f2p, dot2);
    }
}

// ---------------------------------------------------------------------------
// Kernel 2: cost volume. block = 256 consecutive pixels, one depth chunk.
// grid = (NPB, NDCH, B)
// ---------------------------------------------------------------------------
__global__ __launch_bounds__(PIXBLK, 4) void cost_kernel(
    const float* __restrict__ Kref,   // [B,3,3]
    const float* __restrict__ Ksrc,   // [S,B,3,3]
    const float* __restrict__ T,      // [S,B,4,4]
    const float* __restrict__ depths, // [D]
    float* __restrict__ out)          // [B,D,H,W]
{
    const int pix = blockIdx.x * PIXBLK + threadIdx.x;
    const int b = blockIdx.z;
    const int dch = blockIdx.y;
    const int hrow = pix / WW;
    const int wcol = pix - hrow * WW;

    // centered ref features for this pixel -> packed f32x2 register pairs
    u64 f1p[CC / 2];
#pragma unroll
    for (int j = 0; j < CC / 2; j++) {
        float lo = g_f1c[(b * CC + 2 * j + 0) * HWSZ + pix];
        float hi = g_f1c[(b * CC + 2 * j + 1) * HWSZ + pix];
        PACK2(f1p[j], __float_as_uint(lo), __float_as_uint(hi));
    }
    const float n1 = g_n1[b * HWSZ + pix];

    // K^{-1} for this batch
    float Kinv[9];
    inv3x3(Kref + b * 9, Kinv);

    float dh[DCH];
#pragma unroll
    for (int k = 0; k < DCH; k++) dh[k] = depths[dch * DCH + k];

    float cost[DCH];
#pragma unroll
    for (int k = 0; k < DCH; k++) cost[k] = 0.f;

    const float u = (float)wcol;
    const float v = (float)hrow;

    for (int s = 0; s < SS; s++) {
        // M = Ks * R * Kinv ; q = Ks * t
        const float* Tm = T + (s * BB + b) * 16;
        float R[9] = {Tm[0], Tm[1], Tm[2], Tm[4], Tm[5], Tm[6], Tm[8], Tm[9], Tm[10]};
        float t3[3] = {Tm[3], Tm[7], Tm[11]};
        const float* Ks = Ksrc + (s * BB + b) * 9;
        float RK[9], M[9];
        mat3mul(R, Kinv, RK);
        mat3mul(Ks, RK, M);
        float q0 = Ks[0] * t3[0] + Ks[1] * t3[1] + Ks[2] * t3[2];
        float q1 = Ks[3] * t3[0] + Ks[4] * t3[1] + Ks[5] * t3[2];
        float q2 = Ks[6] * t3[0] + Ks[7] * t3[1] + Ks[8] * t3[2];

        // per-pixel homogeneous ray through M (depth-independent part)
        float hp0 = M[0] * u + M[1] * v + M[2];
        float hp1 = M[3] * u + M[4] * v + M[5];
        float hp2 = M[6] * u + M[7] * v + M[8];

        const uint4* sv = g_srcv + (size_t)(s * BB + b) * HWSZ * 2;

        for (int k = 0; k < DCH; k++) {
            float d = dh[k];
            float p0 = fmaf(d, hp0, q0);
            float p1 = fmaf(d, hp1, q1);
            float p2 = fmaf(d, hp2, q2);

            bool valid = p2 > 0.001f;
            float zs = fmaxf(p2, 0.001f);
            float inz = 1.0f / zs;
            float x = p0 * inz;
            float y = p1 * inz;

            float x0f = floorf(x);
            float y0f = floorf(y);
            float fx = x - x0f;
            float fy = y - y0f;
            int x0 = (int)x0f;
            int y0 = (int)y0f;
            int x1 = x0 + 1;
            int y1 = y0 + 1;

            bool okx0 = (x0 >= 0) & (x0 < WW);
            bool okx1 = (x1 >= 0) & (x1 < WW);
            bool oky0 = (y0 >= 0) & (y0 < HH);
            bool oky1 = (y1 >= 0) & (y1 < HH);

            float w00 = (valid & okx0 & oky0) ? (1.f - fx) * (1.f - fy) : 0.f;
            float w01 = (valid & okx1 & oky0) ? fx * (1.f - fy) : 0.f;
            float w10 = (valid & okx0 & oky1) ? (1.f - fx) * fy : 0.f;
            float w11 = (valid & okx1 & oky1) ? fx * fy : 0.f;

            int cx0 = min(max(x0, 0), WW - 1);
            int cx1 = min(max(x1, 0), WW - 1);
            int cy0 = min(max(y0, 0), HH - 1);
            int cy1 = min(max(y1, 0), HH - 1);

            int o00 = 2 * (cy0 * WW + cx0);
            int o01 = 2 * (cy0 * WW + cx1);
            int o10 = 2 * (cy1 * WW + cx0);
            int o11 = 2 * (cy1 * WW + cx1);

            // fp16 broadcast weights
            __half2 w00h = __float2half2_rn(w00);
            __half2 w01h = __float2half2_rn(w01);
            __half2 w10h = __float2half2_rn(w10);
            __half2 w11h = __float2half2_rn(w11);

            u64 sum2 = 0, ssq2 = 0, dot2 = 0;

            // first 8 channels
            {
                uint4 a00 = sv[o00 + 0];
                uint4 a01 = sv[o01 + 0];
                uint4 a10 = sv[o10 + 0];
                uint4 a11 = sv[o11 + 0];
                blend_accum4(a00, a01, a10, a11, w00h, w01h, w10h, w11h,
                             f1p + 0, sum2, ssq2, dot2);
            }
            // last 8 channels
            {
                uint4 a00 = sv[o00 + 1];
                uint4 a01 = sv[o01 + 1];
                uint4 a10 = sv[o10 + 1];
                uint4 a11 = sv[o11 + 1];
                blend_accum4(a00, a01, a10, a11, w00h, w01h, w10h, w11h,
                             f1p + 4, sum2, ssq2, dot2);
            }

            unsigned int lo, hi;
            UNPACK2(lo, hi, sum2);
            float sumf = __uint_as_float(lo) + __uint_as_float(hi);
            UNPACK2(lo, hi, ssq2);
            float ssq = __uint_as_float(lo) + __uint_as_float(hi);
            UNPACK2(lo, hi, dot2);
            float dot = __uint_as_float(lo) + __uint_as_float(hi);

            float n2sq = fmaxf(ssq - sumf * sumf * (1.0f / CC), 0.f);
            float den = fmaf(n1, sqrtf(n2sq), 1e-6f);
            cost[k] += __fdividef(dot, den);
        }
    }

    const float invS = 1.0f / SS;
#pragma unroll
    for (int k = 0; k < DCH; k++) {
        int d = dch * DCH + k;
        out[(b * DD + d) * HWSZ + pix] = cost[k] * invS;
    }
}

extern "C" void kernel_launch(void* const* d_in, const int* in_sizes, int n_in,
                              void* d_out, int out_size) {
    const float* ref_feats = (const float*)d_in[0];
    const float* src_feats = (const float*)d_in[1];
    const float* ref_intr = (const float*)d_in[2];
    const float* src_intr = (const float*)d_in[3];
    const float* ref_to_src = (const float*)d_in[4];
    const float* depths = (const float*)d_in[5];
    float* out = (float*)d_out;

    prep_kernel<<<REF_BLOCKS + SRC_BLOCKS, 256>>>(ref_feats, src_feats);

    dim3 grid(NPB, NDCH, BB);
    cost_kernel<<<grid, PIXBLK>>>(ref_intr, src_intr, ref_to_src, depths, out);
}

// round 6
// speedup vs baseline: 1.9060x; 1.0843x over previous
#include <cuda_runtime.h>
#include <cuda_fp16.h>
#include <math.h>

// Problem constants (match reference setup_inputs)
#define BB 2
#define CC 16
#define CQ (CC / 4)     // channel quads
#define HH 160
#define WW 192
#define SS 3
#define DD 48
#define HWSZ (HH * WW)
#define DCH 6           // depths per block
#define NDCH (DD / DCH) // 8 depth chunks
#define PIXBLK 256
#define NPB (HWSZ / PIXBLK) // 120 pixel-blocks per image

// Packed f32x2 helpers (Blackwell sm_103a)
#define FMA2(d, a, b, c) asm("fma.rn.f32x2 %0, %1, %2, %3;" : "=l"(d) : "l"(a), "l"(b), "l"(c))
#define ADD2(d, a, b)    asm("add.rn.f32x2 %0, %1, %2;"     : "=l"(d) : "l"(a), "l"(b))
#define PACK2(d, lo, hi) asm("mov.b64 %0, {%1, %2};" : "=l"(d) : "r"(lo), "r"(hi))
#define UNPACK2(lo, hi, s) asm("mov.b64 {%0, %1}, %2;" : "=r"(lo), "=r"(hi) : "l"(s))

typedef unsigned long long u64;

// Scratch: centered ref features [B][C][H][W], per-pixel norm [B][H][W],
// and src features in SoA fp16 channel-quad layout:
// [(s,b)][C/4][H*W] of uint2 (4 halves = 4 channels)
__device__ float g_f1c[BB * CC * HWSZ];
__device__ float g_n1[BB * HWSZ];
__device__ uint2 g_srch[SS * BB * CQ * HWSZ];

#define REF_BLOCKS ((BB * HWSZ) / 256)                 // 240
#define SRC_BLOCKS ((SS * BB * CQ * HWSZ) / 256)       // 2880

// ---------------------------------------------------------------------------
// Fused prep: blocks [0,REF_BLOCKS) center ref feats; rest transpose src->fp16
// ---------------------------------------------------------------------------
__global__ void prep_kernel(const float* __restrict__ ref,
                            const float* __restrict__ src) {
    if (blockIdx.x < REF_BLOCKS) {
        int pix = blockIdx.x * 256 + threadIdx.x;
        int b = pix / HWSZ;
        int p = pix - b * HWSZ;

        float v[CC];
        float sum = 0.f;
#pragma unroll
        for (int c = 0; c < CC; c++) {
            v[c] = ref[(b * CC + c) * HWSZ + p];
            sum += v[c];
        }
        float m = sum * (1.0f / CC);
        float ss = 0.f;
#pragma unroll
        for (int c = 0; c < CC; c++) {
            float cv = v[c] - m;
            ss = fmaf(cv, cv, ss);
            g_f1c[(b * CC + c) * HWSZ + p] = cv;
        }
        g_n1[pix] = sqrtf(ss);
    } else {
        int idx = (blockIdx.x - REF_BLOCKS) * 256 + threadIdx.x;
        int pix = idx % HWSZ;
        int t = idx / HWSZ;
        int q = t % CQ;
        int sb = t / CQ;

        const float* base = src + ((size_t)sb * CC + q * 4) * HWSZ + pix;
        __half2 h0 = __floats2half2_rn(base[0 * HWSZ], base[1 * HWSZ]);
        __half2 h1 = __floats2half2_rn(base[2 * HWSZ], base[3 * HWSZ]);
        uint2 v;
        v.x = *reinterpret_cast<unsigned int*>(&h0);
        v.y = *reinterpret_cast<unsigned int*>(&h1);
        g_srch[idx] = v;
    }
}

__device__ __forceinline__ __half2 u2h2(unsigned int u) {
    return *reinterpret_cast<const __half2*>(&u);
}

// 3x3 inverse via adjugate
__device__ __forceinline__ void inv3x3(const float* K, float* I) {
    float a = K[0], b = K[1], c = K[2];
    float d = K[3], e = K[4], f = K[5];
    float g = K[6], h = K[7], i = K[8];
    float A = e * i - f * h;
    float Bm = -(d * i - f * g);
    float Cm = d * h - e * g;
    float det = a * A + b * Bm + c * Cm;
    float rd = 1.0f / det;
    I[0] = A * rd;
    I[1] = -(b * i - c * h) * rd;
    I[2] = (b * f - c * e) * rd;
    I[3] = Bm * rd;
    I[4] = (a * i - c * g) * rd;
    I[5] = -(a * f - c * d) * rd;
    I[6] = Cm * rd;
    I[7] = -(a * h - b * g) * rd;
    I[8] = (a * e - b * d) * rd;
}

__device__ __forceinline__ void mat3mul(const float* A, const float* B, float* C) {
#pragma unroll
    for (int i = 0; i < 3; i++)
#pragma unroll
        for (int j = 0; j < 3; j++)
            C[i * 3 + j] = A[i * 3 + 0] * B[0 * 3 + j] +
                           A[i * 3 + 1] * B[1 * 3 + j] +
                           A[i * 3 + 2] * B[2 * 3 + j];
}

// ---------------------------------------------------------------------------
// Kernel 2: cost volume. block = 256 consecutive pixels, one depth chunk.
// grid = (NPB, NDCH, B)
// ---------------------------------------------------------------------------
__global__ __launch_bounds__(PIXBLK, 4) void cost_kernel(
    const float* __restrict__ Kref,   // [B,3,3]
    const float* __restrict__ Ksrc,   // [S,B,3,3]
    const float* __restrict__ T,      // [S,B,4,4]
    const float* __restrict__ depths, // [D]
    float* __restrict__ out)          // [B,D,H,W]
{
    const int pix = blockIdx.x * PIXBLK + threadIdx.x;
    const int b = blockIdx.z;
    const int dch = blockIdx.y;
    const int hrow = pix / WW;
    const int wcol = pix - hrow * WW;

    // centered ref features for this pixel -> packed f32x2 register pairs
    u64 f1p[CC / 2];
#pragma unroll
    for (int j = 0; j < CC / 2; j++) {
        float lo = g_f1c[(b * CC + 2 * j + 0) * HWSZ + pix];
        float hi = g_f1c[(b * CC + 2 * j + 1) * HWSZ + pix];
        PACK2(f1p[j], __float_as_uint(lo), __float_as_uint(hi));
    }
    const float n1 = g_n1[b * HWSZ + pix];

    // K^{-1} for this batch
    float Kinv[9];
    inv3x3(Kref + b * 9, Kinv);

    float dh[DCH];
#pragma unroll
    for (int k = 0; k < DCH; k++) dh[k] = depths[dch * DCH + k];

    float cost[DCH];
#pragma unroll
    for (int k = 0; k < DCH; k++) cost[k] = 0.f;

    const float u = (float)wcol;
    const float v = (float)hrow;

    for (int s = 0; s < SS; s++) {
        // M = Ks * R * Kinv ; q = Ks * t
        const float* Tm = T + (s * BB + b) * 16;
        float R[9] = {Tm[0], Tm[1], Tm[2], Tm[4], Tm[5], Tm[6], Tm[8], Tm[9], Tm[10]};
        float t3[3] = {Tm[3], Tm[7], Tm[11]};
        const float* Ks = Ksrc + (s * BB + b) * 9;
        float RK[9], M[9];
        mat3mul(R, Kinv, RK);
        mat3mul(Ks, RK, M);
        float q0 = Ks[0] * t3[0] + Ks[1] * t3[1] + Ks[2] * t3[2];
        float q1 = Ks[3] * t3[0] + Ks[4] * t3[1] + Ks[5] * t3[2];
        float q2 = Ks[6] * t3[0] + Ks[7] * t3[1] + Ks[8] * t3[2];

        // per-pixel homogeneous ray through M (depth-independent part)
        float hp0 = M[0] * u + M[1] * v + M[2];
        float hp1 = M[3] * u + M[4] * v + M[5];
        float hp2 = M[6] * u + M[7] * v + M[8];

        const uint2* sp = g_srch + (size_t)(s * BB + b) * CQ * HWSZ;

        for (int k = 0; k < DCH; k++) {
            float d = dh[k];
            float p0 = fmaf(d, hp0, q0);
            float p1 = fmaf(d, hp1, q1);
            float p2 = fmaf(d, hp2, q2);

            bool valid = p2 > 0.001f;
            float zs = fmaxf(p2, 0.001f);
            float inz = 1.0f / zs;
            float x = p0 * inz;
            float y = p1 * inz;

            float x0f = floorf(x);
            float y0f = floorf(y);
            float fx = x - x0f;
            float fy = y - y0f;
            int x0 = (int)x0f;
            int y0 = (int)y0f;
            int x1 = x0 + 1;
            int y1 = y0 + 1;

            bool okx0 = (x0 >= 0) & (x0 < WW);
            bool okx1 = (x1 >= 0) & (x1 < WW);
            bool oky0 = (y0 >= 0) & (y0 < HH);
            bool oky1 = (y1 >= 0) & (y1 < HH);

            float w00 = (valid & okx0 & oky0) ? (1.f - fx) * (1.f - fy) : 0.f;
            float w01 = (valid & okx1 & oky0) ? fx * (1.f - fy) : 0.f;
            float w10 = (valid & okx0 & oky1) ? (1.f - fx) * fy : 0.f;
            float w11 = (valid & okx1 & oky1) ? fx * fy : 0.f;

            int cx0 = min(max(x0, 0), WW - 1);
            int cx1 = min(max(x1, 0), WW - 1);
            int cy0 = min(max(y0, 0), HH - 1);
            int cy1 = min(max(y1, 0), HH - 1);

            // corner base pointers (per-quad offset is an immediate)
            const uint2* p00 = sp + (cy0 * WW + cx0);
            const uint2* p01 = sp + (cy0 * WW + cx1);
            const uint2* p10 = sp + (cy1 * WW + cx0);
            const uint2* p11 = sp + (cy1 * WW + cx1);

            // fp16 broadcast weights
            __half2 w00h = __float2half2_rn(w00);
            __half2 w01h = __float2half2_rn(w01);
            __half2 w10h = __float2half2_rn(w10);
            __half2 w11h = __float2half2_rn(w11);

            u64 sum2 = 0, ssq2 = 0, dot2 = 0;
#pragma unroll
            for (int q = 0; q < CQ; q++) {
                uint2 a00 = p00[q * HWSZ];
                uint2 a01 = p01[q * HWSZ];
                uint2 a10 = p10[q * HWSZ];
                uint2 a11 = p11[q * HWSZ];

                // blend in fp16 (HFMA2), 4 corners per half2 lane
                __half2 f2a = __hmul2(w00h, u2h2(a00.x));
                f2a = __hfma2(w01h, u2h2(a01.x), f2a);
                f2a = __hfma2(w10h, u2h2(a10.x), f2a);
                f2a = __hfma2(w11h, u2h2(a11.x), f2a);
                __half2 f2b = __hmul2(w00h, u2h2(a00.y));
                f2b = __hfma2(w01h, u2h2(a01.y), f2b);
                f2b = __hfma2(w10h, u2h2(a10.y), f2b);
                f2b = __hfma2(w11h, u2h2(a11.y), f2b);

                // convert blended results, accumulate in exact packed fp32
                float2 fa = __half22float2(f2a);
                float2 fb = __half22float2(f2b);
                u64 fpa, fpb;
                PACK2(fpa, __float_as_uint(fa.x), __float_as_uint(fa.y));
                PACK2(fpb, __float_as_uint(fb.x), __float_as_uint(fb.y));

                ADD2(sum2, sum2, fpa);
                ADD2(sum2, sum2, fpb);
                FMA2(ssq2, fpa, fpa, ssq2);
                FMA2(ssq2, fpb, fpb, ssq2);
                FMA2(dot2, f1p[2 * q + 0], fpa, dot2);
                FMA2(dot2, f1p[2 * q + 1], fpb, dot2);
            }

            unsigned int lo, hi;
            UNPACK2(lo, hi, sum2);
            float sumf = __uint_as_float(lo) + __uint_as_float(hi);
            UNPACK2(lo, hi, ssq2);
            float ssq = __uint_as_float(lo) + __uint_as_float(hi);
            UNPACK2(lo, hi, dot2);
            float dot = __uint_as_float(lo) + __uint_as_float(hi);

            float n2sq = fmaxf(ssq - sumf * sumf * (1.0f / CC), 0.f);
            float den = fmaf(n1, sqrtf(n2sq), 1e-6f);
            cost[k] += __fdividef(dot, den);
        }
    }

    const float invS = 1.0f / SS;
#pragma unroll
    for (int k = 0; k < DCH; k++) {
        int d = dch * DCH + k;
        out[(b * DD + d) * HWSZ + pix] = cost[k] * invS;
    }
}

extern "C" void kernel_launch(void* const* d_in, const int* in_sizes, int n_in,
                              void* d_out, int out_size) {
    const float* ref_feats = (const float*)d_in[0];
    const float* src_feats = (const float*)d_in[1];
    const float* ref_intr = (const float*)d_in[2];
    const float* src_intr = (const float*)d_in[3];
    const float* ref_to_src = (const float*)d_in[4];
    const float* depths = (const float*)d_in[5];
    float* out = (float*)d_out;

    prep_kernel<<<REF_BLOCKS + SRC_BLOCKS, 256>>>(ref_feats, src_feats);

    dim3 grid(NPB, NDCH, BB);
    cost_kernel<<<grid, PIXBLK>>>(ref_intr, src_intr, ref_to_src, depths, out);
}

// round 7
// speedup vs baseline: 2.2721x; 1.1921x over previous
#include <cuda_runtime.h>
#include <cuda_fp16.h>
#include <math.h>

// Problem constants (match reference setup_inputs)
#define BB 2
#define CC 16
#define CQ (CC / 4)     // channel quads
#define HH 160
#define WW 192
#define SS 3
#define DD 48
#define HWSZ (HH * WW)
#define WP (WW + 3)     // padded width: cols -1 .. WW+1
#define HP (HH + 3)     // padded height: rows -1 .. HH+1
#define PADSZ (HP * WP)
#define DCH 6           // depths per block
#define NDCH (DD / DCH) // 8 depth chunks
#define PIXBLK 256
#define NPB (HWSZ / PIXBLK) // 120 pixel-blocks per image

// Packed f32x2 helpers (Blackwell sm_103a)
#define FMA2(d, a, b, c) asm("fma.rn.f32x2 %0, %1, %2, %3;" : "=l"(d) : "l"(a), "l"(b), "l"(c))
#define ADD2(d, a, b)    asm("add.rn.f32x2 %0, %1, %2;"     : "=l"(d) : "l"(a), "l"(b))
#define PACK2(d, lo, hi) asm("mov.b64 %0, {%1, %2};" : "=l"(d) : "r"(lo), "r"(hi))
#define UNPACK2(lo, hi, s) asm("mov.b64 {%0, %1}, %2;" : "=r"(lo), "=r"(hi) : "l"(s))

typedef unsigned long long u64;

__device__ __forceinline__ float sqrt_approx(float x) {
    float r;
    asm("sqrt.approx.f32 %0, %1;" : "=f"(r) : "f"(x));
    return r;
}

// Scratch
__device__ float g_f1c[BB * CC * HWSZ];   // centered ref feats [B][C][HW]
__device__ float g_n1[BB * HWSZ];         // ref norms
__device__ uint2 g_srcp[SS * BB * CQ * PADSZ]; // padded fp16 channel-quads
__device__ float g_M[SS * BB * 12];       // per (s,b): M[9], q[3]

#define REF_BLOCKS ((BB * HWSZ) / 256)              // 240
#define SRC_TOTAL (SS * BB * CQ * PADSZ)
#define SRC_BLOCKS ((SRC_TOTAL + 255) / 256)

// ---------------------------------------------------------------------------
// Tiny kernel: per (s,b) fold K_src * R * K_ref^-1 and K_src * t
// ---------------------------------------------------------------------------
__global__ void prep_mat_kernel(const float* __restrict__ Kref,
                                const float* __restrict__ Ksrc,
                                const float* __restrict__ T) {
    int sb = threadIdx.x;
    if (sb >= SS * BB) return;
    int b = sb % BB;

    // inv3x3 of Kref[b]
    const float* K = Kref + b * 9;
    float a = K[0], bb = K[1], c = K[2];
    float d = K[3], e = K[4], f = K[5];
    float g = K[6], h = K[7], i = K[8];
    float A = e * i - f * h;
    float Bm = -(d * i - f * g);
    float Cm = d * h - e * g;
    float det = a * A + bb * Bm + c * Cm;
    float rd = 1.0f / det;
    float I[9];
    I[0] = A * rd;
    I[1] = -(bb * i - c * h) * rd;
    I[2] = (bb * f - c * e) * rd;
    I[3] = Bm * rd;
    I[4] = (a * i - c * g) * rd;
    I[5] = -(a * f - c * d) * rd;
    I[6] = Cm * rd;
    I[7] = -(a * h - bb * g) * rd;
    I[8] = (a * e - bb * d) * rd;

    const float* Tm = T + sb * 16;
    float R[9] = {Tm[0], Tm[1], Tm[2], Tm[4], Tm[5], Tm[6], Tm[8], Tm[9], Tm[10]};
    float t3[3] = {Tm[3], Tm[7], Tm[11]};
    const float* Ks = Ksrc + sb * 9;

    // RK = R * I ; M = Ks * RK
    float RK[9], M[9];
#pragma unroll
    for (int r = 0; r < 3; r++)
#pragma unroll
        for (int cc2 = 0; cc2 < 3; cc2++)
            RK[r * 3 + cc2] = R[r * 3 + 0] * I[0 * 3 + cc2] +
                              R[r * 3 + 1] * I[1 * 3 + cc2] +
                              R[r * 3 + 2] * I[2 * 3 + cc2];
#pragma unroll
    for (int r = 0; r < 3; r++)
#pragma unroll
        for (int cc2 = 0; cc2 < 3; cc2++)
            M[r * 3 + cc2] = Ks[r * 3 + 0] * RK[0 * 3 + cc2] +
                             Ks[r * 3 + 1] * RK[1 * 3 + cc2] +
                             Ks[r * 3 + 2] * RK[2 * 3 + cc2];

    float* o = g_M + sb * 12;
#pragma unroll
    for (int j = 0; j < 9; j++) o[j] = M[j];
    o[9]  = Ks[0] * t3[0] + Ks[1] * t3[1] + Ks[2] * t3[2];
    o[10] = Ks[3] * t3[0] + Ks[4] * t3[1] + Ks[5] * t3[2];
    o[11] = Ks[6] * t3[0] + Ks[7] * t3[1] + Ks[8] * t3[2];
}

// ---------------------------------------------------------------------------
// Fused prep: blocks [0,REF_BLOCKS) center ref feats; rest build padded fp16 src
// ---------------------------------------------------------------------------
__global__ void prep_kernel(const float* __restrict__ ref,
                            const float* __restrict__ src) {
    if (blockIdx.x < REF_BLOCKS) {
        int pix = blockIdx.x * 256 + threadIdx.x;
        int b = pix / HWSZ;
        int p = pix - b * HWSZ;

        float v[CC];
        float sum = 0.f;
#pragma unroll
        for (int c = 0; c < CC; c++) {
            v[c] = ref[(b * CC + c) * HWSZ + p];
            sum += v[c];
        }
        float m = sum * (1.0f / CC);
        float ss = 0.f;
#pragma unroll
        for (int c = 0; c < CC; c++) {
            float cv = v[c] - m;
            ss = fmaf(cv, cv, ss);
            g_f1c[(b * CC + c) * HWSZ + p] = cv;
        }
        g_n1[pix] = sqrtf(ss);
    } else {
        int idx = (blockIdx.x - REF_BLOCKS) * 256 + threadIdx.x;
        if (idx >= SRC_TOTAL) return;
        int px = idx % WP;
        int r1 = idx / WP;
        int py = r1 % HP;
        int t = r1 / HP;
        int q = t % CQ;
        int sb = t / CQ;
        int x = px - 1;
        int y = py - 1;

        uint2 v = make_uint2(0u, 0u);
        if (x >= 0 && x < WW && y >= 0 && y < HH) {
            const float* base = src + ((size_t)sb * CC + q * 4) * HWSZ + y * WW + x;
            __half2 h0 = __floats2half2_rn(base[0 * HWSZ], base[1 * HWSZ]);
            __half2 h1 = __floats2half2_rn(base[2 * HWSZ], base[3 * HWSZ]);
            v.x = *reinterpret_cast<unsigned int*>(&h0);
            v.y = *reinterpret_cast<unsigned int*>(&h1);
        }
        g_srcp[idx] = v;
    }
}

__device__ __forceinline__ __half2 u2h2(unsigned int u) {
    return *reinterpret_cast<const __half2*>(&u);
}

// ---------------------------------------------------------------------------
// Kernel 2: cost volume. block = 256 consecutive pixels, one depth chunk.
// grid = (NPB, NDCH, B)
// ---------------------------------------------------------------------------
__global__ __launch_bounds__(PIXBLK, 4) void cost_kernel(
    const float* __restrict__ depths, // [D]
    float* __restrict__ out)          // [B,D,H,W]
{
    const int pix = blockIdx.x * PIXBLK + threadIdx.x;
    const int b = blockIdx.z;
    const int dch = blockIdx.y;
    const int hrow = pix / WW;
    const int wcol = pix - hrow * WW;

    // centered ref features for this pixel -> packed f32x2 register pairs
    u64 f1p[CC / 2];
#pragma unroll
    for (int j = 0; j < CC / 2; j++) {
        float lo = g_f1c[(b * CC + 2 * j + 0) * HWSZ + pix];
        float hi = g_f1c[(b * CC + 2 * j + 1) * HWSZ + pix];
        PACK2(f1p[j], __float_as_uint(lo), __float_as_uint(hi));
    }
    const float n1 = g_n1[b * HWSZ + pix];

    float dh[DCH];
#pragma unroll
    for (int k = 0; k < DCH; k++) dh[k] = depths[dch * DCH + k];

    float cost[DCH];
#pragma unroll
    for (int k = 0; k < DCH; k++) cost[k] = 0.f;

    const float u = (float)wcol;
    const float v = (float)hrow;

    for (int s = 0; s < SS; s++) {
        const float* mp = g_M + (s * BB + b) * 12;
        float q0 = mp[9], q1 = mp[10], q2 = mp[11];

        // per-pixel homogeneous ray (depth-independent part)
        float hp0 = mp[0] * u + mp[1] * v + mp[2];
        float hp1 = mp[3] * u + mp[4] * v + mp[5];
        float hp2 = mp[6] * u + mp[7] * v + mp[8];

        const uint2* sp = g_srcp + (size_t)(s * BB + b) * CQ * PADSZ;

        for (int k = 0; k < DCH; k++) {
            float d = dh[k];
            float p0 = fmaf(d, hp0, q0);
            float p1 = fmaf(d, hp1, q1);
            float p2 = fmaf(d, hp2, q2);

            bool valid = p2 > 0.001f;
            float zs = fmaxf(p2, 0.001f);
            float inz = __fdividef(1.0f, zs);

            // padded coordinates (origin shift +1 folded into the fma)
            float xp = fmaf(p0, inz, 1.0f);
            float yp = fmaf(p1, inz, 1.0f);
            // clamp into padded domain; out-of-image taps read real zeros
            xp = fminf(fmaxf(xp, 0.0f), (float)(WW + 1));
            yp = fminf(fmaxf(yp, 0.0f), (float)(HH + 1));

            float x0f = floorf(xp);
            float y0f = floorf(yp);
            float fx = xp - x0f;
            float fy = yp - y0f;
            int x0 = (int)x0f;
            int y0 = (int)y0f;

            float wy0 = valid ? (1.f - fy) : 0.f;
            float wy1 = valid ? fy : 0.f;
            float w00 = (1.f - fx) * wy0;
            float w01 = fx * wy0;
            float w10 = (1.f - fx) * wy1;
            float w11 = fx * wy1;

            const uint2* p00 = sp + (y0 * WP + x0);
            const uint2* p01 = p00 + 1;
            const uint2* p10 = p00 + WP;
            const uint2* p11 = p10 + 1;

            // fp16 broadcast weights
            __half2 w00h = __float2half2_rn(w00);
            __half2 w01h = __float2half2_rn(w01);
            __half2 w10h = __float2half2_rn(w10);
            __half2 w11h = __float2half2_rn(w11);

            u64 sum2 = 0, ssq2 = 0, dot2 = 0;
#pragma unroll
            for (int q = 0; q < CQ; q++) {
                uint2 a00 = p00[q * PADSZ];
                uint2 a01 = p01[q * PADSZ];
                uint2 a10 = p10[q * PADSZ];
                uint2 a11 = p11[q * PADSZ];

                // blend in fp16 (HFMA2)
                __half2 f2a = __hmul2(w00h, u2h2(a00.x));
                f2a = __hfma2(w01h, u2h2(a01.x), f2a);
                f2a = __hfma2(w10h, u2h2(a10.x), f2a);
                f2a = __hfma2(w11h, u2h2(a11.x), f2a);
                __half2 f2b = __hmul2(w00h, u2h2(a00.y));
                f2b = __hfma2(w01h, u2h2(a01.y), f2b);
                f2b = __hfma2(w10h, u2h2(a10.y), f2b);
                f2b = __hfma2(w11h, u2h2(a11.y), f2b);

                // convert blended results, accumulate in exact packed fp32
                float2 fa = __half22float2(f2a);
                float2 fb = __half22float2(f2b);
                u64 fpa, fpb;
                PACK2(fpa, __float_as_uint(fa.x), __float_as_uint(fa.y));
                PACK2(fpb, __float_as_uint(fb.x), __float_as_uint(fb.y));

                ADD2(sum2, sum2, fpa);
                ADD2(sum2, sum2, fpb);
                FMA2(ssq2, fpa, fpa, ssq2);
                FMA2(ssq2, fpb, fpb, ssq2);
                FMA2(dot2, f1p[2 * q + 0], fpa, dot2);
                FMA2(dot2, f1p[2 * q + 1], fpb, dot2);
            }

            unsigned int lo, hi;
            UNPACK2(lo, hi, sum2);
            float sumf = __uint_as_float(lo) + __uint_as_float(hi);
            UNPACK2(lo, hi, ssq2);
            float ssq = __uint_as_float(lo) + __uint_as_float(hi);
            UNPACK2(lo, hi, dot2);
            float dot = __uint_as_float(lo) + __uint_as_float(hi);

            float n2sq = fmaxf(fmaf(-sumf * (1.0f / CC), sumf, ssq), 0.f);
            float den = fmaf(n1, sqrt_approx(n2sq), 1e-6f);
            cost[k] += __fdividef(dot, den);
        }
    }

    const float invS = 1.0f / SS;
#pragma unroll
    for (int k = 0; k < DCH; k++) {
        int d = dch * DCH + k;
        out[(b * DD + d) * HWSZ + pix] = cost[k] * invS;
    }
}

extern "C" void kernel_launch(void* const* d_in, const int* in_sizes, int n_in,
                              void* d_out, int out_size) {
    const float* ref_feats = (const float*)d_in[0];
    const float* src_feats = (const float*)d_in[1];
    const float* ref_intr = (const float*)d_in[2];
    const float* src_intr = (const float*)d_in[3];
    const float* ref_to_src = (const float*)d_in[4];
    const float* depths = (const float*)d_in[5];
    float* out = (float*)d_out;

    prep_mat_kernel<<<1, 32>>>(ref_intr, src_intr, ref_to_src);
    prep_kernel<<<REF_BLOCKS + SRC_BLOCKS, 256>>>(ref_feats, src_feats);

    dim3 grid(NPB, NDCH, BB);
    cost_kernel<<<grid, PIXBLK>>>(depths, out);
}

// round 8
// speedup vs baseline: 2.5011x; 1.1008x over previous
#include <cuda_runtime.h>
#include <cuda_fp16.h>
#include <math.h>

// Problem constants (match reference setup_inputs)
#define BB 2
#define CC 16
#define CQ (CC / 4)     // channel quads
#define HH 160
#define WW 192
#define SS 3
#define DD 48
#define HWSZ (HH * WW)
#define WP (WW + 3)     // padded width: cols -1 .. WW+1
#define HP (HH + 3)     // padded height: rows -1 .. HH+1
#define PADSZ (HP * WP)
#define DCH 6           // depths per block
#define NDCH (DD / DCH) // 8 depth chunks
#define PIXBLK 256
#define NPB (HWSZ / PIXBLK) // 120 pixel-blocks per image

// Packed f32x2 helpers (Blackwell sm_103a)
#define FMA2(d, a, b, c) asm("fma.rn.f32x2 %0, %1, %2, %3;" : "=l"(d) : "l"(a), "l"(b), "l"(c))
#define PACK2(d, lo, hi) asm("mov.b64 %0, {%1, %2};" : "=l"(d) : "r"(lo), "r"(hi))
#define UNPACK2(lo, hi, s) asm("mov.b64 {%0, %1}, %2;" : "=r"(lo), "=r"(hi) : "l"(s))

typedef unsigned long long u64;

__device__ __forceinline__ float sqrt_approx(float x) {
    float r;
    asm("sqrt.approx.f32 %0, %1;" : "=f"(r) : "f"(x));
    return r;
}

// Scratch
__device__ float g_f1c[BB * CC * HWSZ];        // centered ref feats [B][C][HW]
__device__ float g_n1[BB * HWSZ];              // ref norms
__device__ uint2 g_srcp[SS * BB * CQ * PADSZ]; // padded, PRE-CENTERED fp16 quads
__device__ float g_M[SS * BB * 12];            // per (s,b): M[9], q[3]

#define REF_BLOCKS ((BB * HWSZ) / 256)                  // 240
#define SRC_PIX_TOTAL (SS * BB * PADSZ)
#define SRC_BLOCKS ((SRC_PIX_TOTAL + 255) / 256)

// ---------------------------------------------------------------------------
// Fused prep:
//   block 0 thread<6:          fold K_src*R*K_ref^-1 and K_src*t into g_M
//   blocks [0,REF_BLOCKS):     center ref feats + norm
//   remaining blocks:          padded, per-pixel-centered fp16 src quads
// ---------------------------------------------------------------------------
__global__ void prep_kernel(const float* __restrict__ ref,
                            const float* __restrict__ src,
                            const float* __restrict__ Kref,
                            const float* __restrict__ Ksrc,
                            const float* __restrict__ T) {
    if (blockIdx.x == 0 && threadIdx.x >= 224) {
        int sb = threadIdx.x - 224;
        if (sb < SS * BB) {
            int b = sb % BB;
            const float* K = Kref + b * 9;
            float a = K[0], bb = K[1], c = K[2];
            float d = K[3], e = K[4], f = K[5];
            float g = K[6], h = K[7], i = K[8];
            float A = e * i - f * h;
            float Bm = -(d * i - f * g);
            float Cm = d * h - e * g;
            float det = a * A + bb * Bm + c * Cm;
            float rd = 1.0f / det;
            float I[9];
            I[0] = A * rd;
            I[1] = -(bb * i - c * h) * rd;
            I[2] = (bb * f - c * e) * rd;
            I[3] = Bm * rd;
            I[4] = (a * i - c * g) * rd;
            I[5] = -(a * f - c * d) * rd;
            I[6] = Cm * rd;
            I[7] = -(a * h - bb * g) * rd;
            I[8] = (a * e - bb * d) * rd;

            const float* Tm = T + sb * 16;
            float R[9] = {Tm[0], Tm[1], Tm[2], Tm[4], Tm[5], Tm[6], Tm[8], Tm[9], Tm[10]};
            float t3[3] = {Tm[3], Tm[7], Tm[11]};
            const float* Ks = Ksrc + sb * 9;

            float RK[9], M[9];
#pragma unroll
            for (int r = 0; r < 3; r++)
#pragma unroll
                for (int c2 = 0; c2 < 3; c2++)
                    RK[r * 3 + c2] = R[r * 3 + 0] * I[0 * 3 + c2] +
                                     R[r * 3 + 1] * I[1 * 3 + c2] +
                                     R[r * 3 + 2] * I[2 * 3 + c2];
#pragma unroll
            for (int r = 0; r < 3; r++)
#pragma unroll
                for (int c2 = 0; c2 < 3; c2++)
                    M[r * 3 + c2] = Ks[r * 3 + 0] * RK[0 * 3 + c2] +
                                    Ks[r * 3 + 1] * RK[1 * 3 + c2] +
                                    Ks[r * 3 + 2] * RK[2 * 3 + c2];

            float* o = g_M + sb * 12;
#pragma unroll
            for (int j = 0; j < 9; j++) o[j] = M[j];
            o[9]  = Ks[0] * t3[0] + Ks[1] * t3[1] + Ks[2] * t3[2];
            o[10] = Ks[3] * t3[0] + Ks[4] * t3[1] + Ks[5] * t3[2];
            o[11] = Ks[6] * t3[0] + Ks[7] * t3[1] + Ks[8] * t3[2];
        }
    }

    if (blockIdx.x < REF_BLOCKS) {
        // ref centering (blocks 0..239; block 0's high warp also did matrices,
        // but every thread still does its ref pixel — no divergence issue)
        int pix = blockIdx.x * 256 + threadIdx.x;
        int b = pix / HWSZ;
        int p = pix - b * HWSZ;

        float v[CC];
        float sum = 0.f;
#pragma unroll
        for (int c = 0; c < CC; c++) {
            v[c] = ref[(b * CC + c) * HWSZ + p];
            sum += v[c];
        }
        float m = sum * (1.0f / CC);
        float ss = 0.f;
#pragma unroll
        for (int c = 0; c < CC; c++) {
            float cv = v[c] - m;
            ss = fmaf(cv, cv, ss);
            g_f1c[(b * CC + c) * HWSZ + p] = cv;
        }
        g_n1[pix] = sqrtf(ss);
    } else {
        // src: one thread per padded pixel; center across channels, store quads
        int idx = (blockIdx.x - REF_BLOCKS) * 256 + threadIdx.x;
        if (idx >= SRC_PIX_TOTAL) return;
        int px = idx % WP;
        int r1 = idx / WP;
        int py = r1 % HP;
        int sb = r1 / HP;
        int x = px - 1;
        int y = py - 1;

        uint2 vq[CQ];
        if (x >= 0 && x < WW && y >= 0 && y < HH) {
            const float* base = src + (size_t)sb * CC * HWSZ + y * WW + x;
            float v[CC];
            float sum = 0.f;
#pragma unroll
            for (int c = 0; c < CC; c++) {
                v[c] = base[c * HWSZ];
                sum += v[c];
            }
            float m = sum * (1.0f / CC);
#pragma unroll
            for (int q = 0; q < CQ; q++) {
                __half2 h0 = __floats2half2_rn(v[q * 4 + 0] - m, v[q * 4 + 1] - m);
                __half2 h1 = __floats2half2_rn(v[q * 4 + 2] - m, v[q * 4 + 3] - m);
                vq[q].x = *reinterpret_cast<unsigned int*>(&h0);
                vq[q].y = *reinterpret_cast<unsigned int*>(&h1);
            }
        } else {
#pragma unroll
            for (int q = 0; q < CQ; q++) vq[q] = make_uint2(0u, 0u);
        }
        size_t base_out = (size_t)sb * CQ * PADSZ + py * WP + px;
#pragma unroll
        for (int q = 0; q < CQ; q++)
            g_srcp[base_out + q * PADSZ] = vq[q];
    }
}

__device__ __forceinline__ __half2 u2h2(unsigned int u) {
    return *reinterpret_cast<const __half2*>(&u);
}

// ---------------------------------------------------------------------------
// Kernel 2: cost volume. block = 256 consecutive pixels, one depth chunk.
// grid = (NPB, NDCH, B)
// ---------------------------------------------------------------------------
__global__ __launch_bounds__(PIXBLK, 4) void cost_kernel(
    const float* __restrict__ depths, // [D]
    float* __restrict__ out)          // [B,D,H,W]
{
    const int pix = blockIdx.x * PIXBLK + threadIdx.x;
    const int b = blockIdx.z;
    const int dch = blockIdx.y;
    const int hrow = pix / WW;
    const int wcol = pix - hrow * WW;

    // centered ref features for this pixel -> packed f32x2 register pairs
    u64 f1p[CC / 2];
#pragma unroll
    for (int j = 0; j < CC / 2; j++) {
        float lo = g_f1c[(b * CC + 2 * j + 0) * HWSZ + pix];
        float hi = g_f1c[(b * CC + 2 * j + 1) * HWSZ + pix];
        PACK2(f1p[j], __float_as_uint(lo), __float_as_uint(hi));
    }
    const float n1 = g_n1[b * HWSZ + pix];

    float dh[DCH];
#pragma unroll
    for (int k = 0; k < DCH; k++) dh[k] = depths[dch * DCH + k];

    float cost[DCH];
#pragma unroll
    for (int k = 0; k < DCH; k++) cost[k] = 0.f;

    const float u = (float)wcol;
    const float v = (float)hrow;

    for (int s = 0; s < SS; s++) {
        const float* mp = g_M + (s * BB + b) * 12;
        float q0 = mp[9], q1 = mp[10], q2 = mp[11];

        // per-pixel homogeneous ray (depth-independent part)
        float hp0 = mp[0] * u + mp[1] * v + mp[2];
        float hp1 = mp[3] * u + mp[4] * v + mp[5];
        float hp2 = mp[6] * u + mp[7] * v + mp[8];

        const uint2* sp = g_srcp + (size_t)(s * BB + b) * CQ * PADSZ;

        for (int k = 0; k < DCH; k++) {
            float d = dh[k];
            float p0 = fmaf(d, hp0, q0);
            float p1 = fmaf(d, hp1, q1);
            float p2 = fmaf(d, hp2, q2);

            bool valid = p2 > 0.001f;
            float zs = fmaxf(p2, 0.001f);
            float inz = __fdividef(1.0f, zs);

            // padded coordinates (origin shift +1 folded into the fma)
            float xp = fmaf(p0, inz, 1.0f);
            float yp = fmaf(p1, inz, 1.0f);
            // clamp into padded domain; out-of-image taps read real zeros
            xp = fminf(fmaxf(xp, 0.0f), (float)(WW + 1));
            yp = fminf(fmaxf(yp, 0.0f), (float)(HH + 1));

            float x0f = floorf(xp);
            float y0f = floorf(yp);
            float fx = xp - x0f;
            float fy = yp - y0f;
            int x0 = (int)x0f;
            int y0 = (int)y0f;

            float wy0 = valid ? (1.f - fy) : 0.f;
            float wy1 = valid ? fy : 0.f;
            float w00 = (1.f - fx) * wy0;
            float w01 = fx * wy0;
            float w10 = (1.f - fx) * wy1;
            float w11 = fx * wy1;

            const uint2* p00 = sp + (y0 * WP + x0);
            const uint2* p01 = p00 + 1;
            const uint2* p10 = p00 + WP;
            const uint2* p11 = p10 + 1;

            // fp16 broadcast weights
            __half2 w00h = __float2half2_rn(w00);
            __half2 w01h = __float2half2_rn(w01);
            __half2 w10h = __float2half2_rn(w10);
            __half2 w11h = __float2half2_rn(w11);

            u64 ssq2 = 0, dot2 = 0;
#pragma unroll
            for (int q = 0; q < CQ; q++) {
                uint2 a00 = p00[q * PADSZ];
                uint2 a01 = p01[q * PADSZ];
                uint2 a10 = p10[q * PADSZ];
                uint2 a11 = p11[q * PADSZ];

                // blend pre-centered fp16 features (result IS the centered f2)
                __half2 f2a = __hmul2(w00h, u2h2(a00.x));
                f2a = __hfma2(w01h, u2h2(a01.x), f2a);
                f2a = __hfma2(w10h, u2h2(a10.x), f2a);
                f2a = __hfma2(w11h, u2h2(a11.x), f2a);
                __half2 f2b = __hmul2(w00h, u2h2(a00.y));
                f2b = __hfma2(w01h, u2h2(a01.y), f2b);
                f2b = __hfma2(w10h, u2h2(a10.y), f2b);
                f2b = __hfma2(w11h, u2h2(a11.y), f2b);

                // convert blended results, accumulate in exact packed fp32
                float2 fa = __half22float2(f2a);
                float2 fb = __half22float2(f2b);
                u64 fpa, fpb;
                PACK2(fpa, __float_as_uint(fa.x), __float_as_uint(fa.y));
                PACK2(fpb, __float_as_uint(fb.x), __float_as_uint(fb.y));

                FMA2(ssq2, fpa, fpa, ssq2);
                FMA2(ssq2, fpb, fpb, ssq2);
                FMA2(dot2, f1p[2 * q + 0], fpa, dot2);
                FMA2(dot2, f1p[2 * q + 1], fpb, dot2);
            }

            unsigned int lo, hi;
            UNPACK2(lo, hi, ssq2);
            float n2sq = __uint_as_float(lo) + __uint_as_float(hi);
            UNPACK2(lo, hi, dot2);
            float dot = __uint_as_float(lo) + __uint_as_float(hi);

            float den = fmaf(n1, sqrt_approx(n2sq), 1e-6f);
            cost[k] += __fdividef(dot, den);
        }
    }

    const float invS = 1.0f / SS;
#pragma unroll
    for (int k = 0; k < DCH; k++) {
        int d = dch * DCH + k;
        out[(b * DD + d) * HWSZ + pix] = cost[k] * invS;
    }
}

extern "C" void kernel_launch(void* const* d_in, const int* in_sizes, int n_in,
                              void* d_out, int out_size) {
    const float* ref_feats = (const float*)d_in[0];
    const float* src_feats = (const float*)d_in[1];
    const float* ref_intr = (const float*)d_in[2];
    const float* src_intr = (const float*)d_in[3];
    const float* ref_to_src = (const float*)d_in[4];
    const float* depths = (const float*)d_in[5];
    float* out = (float*)d_out;

    prep_kernel<<<REF_BLOCKS + SRC_BLOCKS, 256>>>(
        ref_feats, src_feats, ref_intr, src_intr, ref_to_src);

    dim3 grid(NPB, NDCH, BB);
    cost_kernel<<<grid, PIXBLK>>>(depths, out);
}